// round 10
// baseline (speedup 1.0000x reference)
#include <cuda_runtime.h>
#include <math.h>
#include <stdint.h>

#define Nn 10000
#define Dn 15
#define Ln 16
#define Ee 320
#define OUTD 30
#define NH 5
#define HD 64

// ---------------- scratch (static device globals; no allocation) ----------------
__device__ float g_Mq_in[Ee*Ee], g_Mk_in[Ee*Ee], g_Mv_in[Ee*Ee];
__device__ float g_Mq_out[Ee*Ee], g_Mk_out[Ee*Ee], g_Mv_out[Ee*Ee];
__device__ float g_Qmat[Ee*Ee], g_Kmat_in[Ee*Ee], g_Kmat_out[Ee*Ee];
__device__ float g_Vmat_in[Ee*Ee], g_Vmat_out[Ee*Ee];
__device__ float g_T_in_o[Ee*Ee], g_T_out_o[Ee*Ee], g_T_fin_o[Ee*Ee];
__device__ float g_qbias[Ee], g_kbias_in[Ee], g_kbias_out[Ee], g_vbias_in[Ee], g_vbias_out[Ee];
__device__ float g_Fmat[Ee*OUTD], g_fbias[OUTD];
__device__ int   g_rows_in[Nn*Ln], g_rows_out[Nn*Ln], g_rows_q0[Nn];
__device__ float g_Q[(size_t)Nn*Ln*Ee], g_K[(size_t)Nn*Ln*Ee], g_V[(size_t)Nn*Ln*Ee];
__device__ float g_Oin[(size_t)Nn*Ln*Ee], g_Oout[(size_t)Nn*Ln*Ee];
__device__ float g_Kf[(size_t)Nn*2*Ln*Ee], g_Vf[(size_t)Nn*2*Ln*Ee];
__device__ float g_q0[(size_t)Nn*Ee];

// ---------------- helpers ----------------
__device__ __forceinline__ void mma_tf32(float* d, const uint32_t* a, uint32_t b0, uint32_t b1) {
    asm volatile(
        "mma.sync.aligned.m16n8k8.row.col.f32.tf32.tf32.f32 "
        "{%0,%1,%2,%3}, {%4,%5,%6,%7}, {%8,%9}, {%0,%1,%2,%3};"
        : "+f"(d[0]), "+f"(d[1]), "+f"(d[2]), "+f"(d[3])
        : "r"(a[0]), "r"(a[1]), "r"(a[2]), "r"(a[3]), "r"(b0), "r"(b1));
}

__device__ __forceinline__ void cp_async16(void* smem_dst, const void* gmem_src) {
    uint32_t d = (uint32_t)__cvta_generic_to_shared(smem_dst);
    asm volatile("cp.async.cg.shared.global [%0], [%1], 16;" :: "r"(d), "l"(gmem_src));
}
__device__ __forceinline__ void cp_commit() {
    asm volatile("cp.async.commit_group;" ::: "memory");
}

// ---------------- precompute kernels ----------------

__global__ void transpose320(const float* __restrict__ in, float* __restrict__ out) {
    __shared__ float tile[32][33];
    int bx = blockIdx.x * 32, by = blockIdx.y * 32;
    int x = bx + threadIdx.x;
    #pragma unroll
    for (int i = 0; i < 32; i += 8) {
        int y = by + threadIdx.y + i;
        tile[threadIdx.y + i][threadIdx.x] = in[(size_t)y*Ee + x];
    }
    __syncthreads();
    x = by + threadIdx.x;
    #pragma unroll
    for (int i = 0; i < 32; i += 8) {
        int y = bx + threadIdx.y + i;
        out[(size_t)y*Ee + x] = tile[threadIdx.x][threadIdx.y + i];
    }
}

#define NCOMB 11
struct CombineBatch {
    const float* A[NCOMB];
    const float* B[NCOMB];
    float*       C[NCOMB];
};
__global__ void __launch_bounds__(256) combine_batch(CombineBatch p) {
    const float* __restrict__ A = p.A[blockIdx.z];
    const float* __restrict__ B = p.B[blockIdx.z];
    float* __restrict__ C = p.C[blockIdx.z];
    constexpr int BK = 16;
    __shared__ float As[BK][64];
    __shared__ float Bs[BK][64];
    const int tid = threadIdx.x;
    const int bm = blockIdx.y * 64;
    const int bn = blockIdx.x * 64;
    const int tcol = tid & 15, trow = tid >> 4;
    const int aRow = tid >> 2, aCol = (tid & 3) << 2;

    float acc[4][4];
    #pragma unroll
    for (int i = 0; i < 4; i++)
        #pragma unroll
        for (int j = 0; j < 4; j++) acc[i][j] = 0.f;

    for (int k0 = 0; k0 < Ee; k0 += BK) {
        float4 a4 = *(const float4*)(A + (size_t)(bm + aRow)*Ee + k0 + aCol);
        float4 b4 = *(const float4*)(B + (size_t)(bn + aRow)*Ee + k0 + aCol);
        As[aCol+0][aRow] = a4.x; As[aCol+1][aRow] = a4.y;
        As[aCol+2][aRow] = a4.z; As[aCol+3][aRow] = a4.w;
        Bs[aCol+0][aRow] = b4.x; Bs[aCol+1][aRow] = b4.y;
        Bs[aCol+2][aRow] = b4.z; Bs[aCol+3][aRow] = b4.w;
        __syncthreads();
        #pragma unroll
        for (int kk = 0; kk < BK; kk++) {
            float ar[4], br[4];
            #pragma unroll
            for (int i = 0; i < 4; i++) ar[i] = As[kk][trow*4 + i];
            #pragma unroll
            for (int j = 0; j < 4; j++) br[j] = Bs[kk][tcol*4 + j];
            #pragma unroll
            for (int i = 0; i < 4; i++)
                #pragma unroll
                for (int j = 0; j < 4; j++)
                    acc[i][j] += ar[i] * br[j];
        }
        __syncthreads();
    }
    #pragma unroll
    for (int i = 0; i < 4; i++)
        #pragma unroll
        for (int j = 0; j < 4; j++)
            C[(size_t)(bm + trow*4 + i)*Ee + bn + tcol*4 + j] = acc[i][j];
}

#define NBIAS 5
struct BiasBatch {
    const float* bo[NBIAS];
    const float* Bq[NBIAS];
    const float* b2[NBIAS];
    float*       out[NBIAS];
};
__global__ void __launch_bounds__(256) bias_batch(BiasBatch p) {
    int task = blockIdx.y;
    const float* __restrict__ bo = p.bo[task];
    const float* __restrict__ Bq = p.Bq[task];
    int j = (blockIdx.x * 256 + threadIdx.x) >> 5;
    int lane = threadIdx.x & 31;
    if (j >= Ee) return;
    const float* br = Bq + (size_t)j*Ee;
    float s = 0.f;
    #pragma unroll
    for (int e = lane, i = 0; i < Ee/32; e += 32, i++) s += bo[e] * br[e];
    #pragma unroll
    for (int off = 16; off > 0; off >>= 1) s += __shfl_down_sync(0xffffffffu, s, off);
    if (lane == 0) p.out[task][j] = s + p.b2[task][j];
}

__global__ void combine_fmat_w(const float* __restrict__ fowT, const float* __restrict__ W,
                               float* __restrict__ out) {
    int o = (blockIdx.x * 256 + threadIdx.x) >> 5;
    int lane = threadIdx.x & 31;
    if (o >= Ee*OUTD) return;
    int e = o / OUTD, j = o % OUTD;
    const float* fr = fowT + (size_t)e*Ee;
    float s = 0.f;
    #pragma unroll
    for (int t = lane, i = 0; i < Ee/32; t += 32, i++) s += fr[t] * W[(size_t)t*OUTD + j];
    #pragma unroll
    for (int off = 16; off > 0; off >>= 1) s += __shfl_down_sync(0xffffffffu, s, off);
    if (lane == 0) out[o] = s;
}

__global__ void combine_fbias_w(const float* __restrict__ fob, const float* __restrict__ W,
                                float* __restrict__ out) {
    int warp = threadIdx.x >> 5, lane = threadIdx.x & 31;
    for (int j = warp; j < OUTD; j += 8) {
        float s = 0.f;
        #pragma unroll
        for (int t = lane, i = 0; i < Ee/32; t += 32, i++) s += fob[t] * W[(size_t)t*OUTD + j];
        #pragma unroll
        for (int off = 16; off > 0; off >>= 1) s += __shfl_down_sync(0xffffffffu, s, off);
        if (lane == 0) out[j] = s;
    }
}

__global__ void build_rows(const int* __restrict__ in_idx, const int* __restrict__ out_idx,
                           int* __restrict__ rin, int* __restrict__ rout, int* __restrict__ rq0) {
    int n = blockIdx.x * blockDim.x + threadIdx.x;
    if (n >= Nn) return;
    rin[n*Ln] = n;
    rout[n*Ln] = n;
    rq0[n] = n*Ln;
    #pragma unroll
    for (int d = 0; d < Dn; d++) {
        rin[n*Ln + 1 + d]  = in_idx[n*Dn + d];
        rout[n*Ln + 1 + d] = out_idx[n*Dn + d];
    }
}

// ---------------- tensor-core multi-B GEMM, 3-stage cp.async pipeline ----------------
// tf32 HMMA (fp32 bits fed directly; HW truncates), fp32 accumulate.
// BM=128, BN=64, BK=32, 3 stages, ONE __syncthreads per k-iter. M % 128 == 0.
template<int NMAT>
__global__ void __launch_bounds__(256) gemm_tc(
    const float* __restrict__ A, const int* __restrict__ rows,
    const float* __restrict__ B0, const float* __restrict__ B1, const float* __restrict__ B2,
    const float* __restrict__ bias0, const float* __restrict__ bias1, const float* __restrict__ bias2,
    float* __restrict__ C0, float* __restrict__ C1, float* __restrict__ C2,
    int out_grp, int out_str, int out_off)
{
    constexpr int BM = 128, BN = 64, BK = 32;
    constexpr int ASTR = 36;
    constexpr int BSTR = 72;
    constexpr int NT = Ee / BK;        // 10
    constexpr int STG = 3;
    constexpr int ASTAGE = BM*ASTR;
    constexpr int BSTAGE = BK*BSTR;
    extern __shared__ float smp[];
    float* AsBase = smp;                          // [STG][ASTAGE]
    float* BsBase = smp + STG*ASTAGE;             // [STG][NMAT][BSTAGE]

    const int tid = threadIdx.x;
    const int bm = blockIdx.y * BM;
    const int bn = blockIdx.x * BN;
    const int warpId = tid >> 5, lane = tid & 31;
    const int wm = (warpId & 3) * 32;
    const int wn = (warpId >> 2) * 32;
    const int g = lane >> 2, t = lane & 3;

    const float* Bp[NMAT]; const float* biasp[NMAT]; float* Cp[NMAT];
    Bp[0] = B0; biasp[0] = bias0; Cp[0] = C0;
    if (NMAT > 1) { Bp[1] = B1; biasp[1] = bias1; Cp[1] = C1; }
    if (NMAT > 2) { Bp[2] = B2; biasp[2] = bias2; Cp[2] = C2; }

    float acc[NMAT][2][4][4];
    #pragma unroll
    for (int q = 0; q < NMAT; q++)
        #pragma unroll
        for (int mi = 0; mi < 2; mi++)
            #pragma unroll
            for (int ni = 0; ni < 4; ni++)
                #pragma unroll
                for (int v = 0; v < 4; v++) acc[q][mi][ni][v] = 0.f;

    const int aRow = tid >> 3;
    const int aCol = (tid & 7) * 4;
    size_t gA[4];
    #pragma unroll
    for (int i = 0; i < 4; i++) {
        int m = bm + aRow + i*32;
        gA[i] = (size_t)(rows ? rows[m] : m) * Ee;
    }
    const int bRow = tid >> 4;
    const int bCol = (tid & 15) * 4;

    auto issue = [&](int kt, int st) {
        float* As = AsBase + st*ASTAGE;
        #pragma unroll
        for (int i = 0; i < 4; i++)
            cp_async16(&As[(aRow + i*32)*ASTR + aCol], A + gA[i] + kt*BK + aCol);
        #pragma unroll
        for (int q = 0; q < NMAT; q++) {
            float* Bs = BsBase + (st*NMAT + q)*BSTAGE;
            #pragma unroll
            for (int i = 0; i < 2; i++) {
                int kr = bRow + i*16;
                cp_async16(&Bs[kr*BSTR + bCol], Bp[q] + (size_t)(kt*BK + kr)*Ee + bn + bCol);
            }
        }
        cp_commit();
    };

    auto compute = [&](int st) {
        const float* As = AsBase + st*ASTAGE;
        #pragma unroll
        for (int kk = 0; kk < BK; kk += 8) {
            uint32_t afr[2][4];
            #pragma unroll
            for (int mi = 0; mi < 2; mi++) {
                int r0 = wm + mi*16 + g;
                afr[mi][0] = __float_as_uint(As[(r0    )*ASTR + kk + t    ]);
                afr[mi][1] = __float_as_uint(As[(r0 + 8)*ASTR + kk + t    ]);
                afr[mi][2] = __float_as_uint(As[(r0    )*ASTR + kk + t + 4]);
                afr[mi][3] = __float_as_uint(As[(r0 + 8)*ASTR + kk + t + 4]);
            }
            #pragma unroll
            for (int q = 0; q < NMAT; q++) {
                const float* Bs = BsBase + (st*NMAT + q)*BSTAGE;
                #pragma unroll
                for (int ni = 0; ni < 4; ni++) {
                    int nc = wn + ni*8 + g;
                    uint32_t b0 = __float_as_uint(Bs[(kk + t    )*BSTR + nc]);
                    uint32_t b1 = __float_as_uint(Bs[(kk + t + 4)*BSTR + nc]);
                    #pragma unroll
                    for (int mi = 0; mi < 2; mi++)
                        mma_tf32(acc[q][mi][ni], afr[mi], b0, b1);
                }
            }
        }
    };

    // 3-stage pipeline: 2 tiles prefetched ahead; one barrier per iteration.
    issue(0, 0);
    issue(1, 1);

    #pragma unroll 1
    for (int kt = 0; kt < NT; kt++) {
        if (kt + 1 < NT) {
            asm volatile("cp.async.wait_group 1;" ::: "memory");
        } else {
            asm volatile("cp.async.wait_group 0;" ::: "memory");
        }
        __syncthreads();   // stage kt%3 ready for all; stage (kt+2)%3 free (computed at kt-1)
        if (kt + 2 < NT) issue(kt + 2, (kt + 2) % STG);
        compute(kt % STG);
    }

    // epilogue
    #pragma unroll
    for (int q = 0; q < NMAT; q++) {
        #pragma unroll
        for (int ni = 0; ni < 4; ni++) {
            int n = bn + wn + ni*8 + 2*t;
            float bb0 = biasp[q][n], bb1 = biasp[q][n+1];
            #pragma unroll
            for (int mi = 0; mi < 2; mi++) {
                int m0 = bm + wm + mi*16 + g;
                int m1 = m0 + 8;
                int cr0 = (m0 / out_grp) * out_str + (m0 % out_grp) + out_off;
                int cr1 = (m1 / out_grp) * out_str + (m1 % out_grp) + out_off;
                float2 v0, v1;
                v0.x = acc[q][mi][ni][0] + bb0; v0.y = acc[q][mi][ni][1] + bb1;
                v1.x = acc[q][mi][ni][2] + bb0; v1.y = acc[q][mi][ni][3] + bb1;
                *(float2*)(Cp[q] + (size_t)cr0*Ee + n) = v0;
                *(float2*)(Cp[q] + (size_t)cr1*Ee + n) = v1;
            }
        }
    }
}

// ---------------- single-B SIMT GEMM with M guard (q0: M = 10000, fp32 exact) ----------------
__global__ void __launch_bounds__(256) gemm320(
    const float* __restrict__ A, const int* __restrict__ rows, int M,
    const float* __restrict__ B, const float* __restrict__ bias,
    float* __restrict__ C)
{
    constexpr int BM = 64, BN = 64, BK = 16;
    __shared__ float As[BK][BM];
    __shared__ float Bs[BK][BN];
    const int tid = threadIdx.x;
    const int bm = blockIdx.y * BM;
    const int bn = blockIdx.x * BN;
    const int tcol = tid & 15;
    const int trow = tid >> 4;

    float acc[4][4];
    #pragma unroll
    for (int i = 0; i < 4; i++)
        #pragma unroll
        for (int j = 0; j < 4; j++) acc[i][j] = 0.f;

    const int aRow = tid >> 2;
    const int aCol = (tid & 3) << 2;
    int r = bm + aRow; if (r >= M) r = M - 1;
    const size_t ga = (size_t)(rows ? rows[r] : r) * Ee;
    const int bRow = tid >> 4;
    const int bCol = (tid & 15) << 2;

    for (int k0 = 0; k0 < Ee; k0 += BK) {
        float4 a4 = *(const float4*)(A + ga + k0 + aCol);
        float4 b4 = *(const float4*)(B + (size_t)(k0 + bRow)*Ee + bn + bCol);
        As[aCol+0][aRow] = a4.x; As[aCol+1][aRow] = a4.y;
        As[aCol+2][aRow] = a4.z; As[aCol+3][aRow] = a4.w;
        *(float4*)&Bs[bRow][bCol] = b4;
        __syncthreads();

        #pragma unroll
        for (int kk = 0; kk < BK; kk++) {
            float ar[4], br[4];
            #pragma unroll
            for (int i = 0; i < 4; i++) ar[i] = As[kk][trow*4 + i];
            #pragma unroll
            for (int j = 0; j < 4; j++) br[j] = Bs[kk][tcol*4 + j];
            #pragma unroll
            for (int i = 0; i < 4; i++)
                #pragma unroll
                for (int j = 0; j < 4; j++)
                    acc[i][j] += ar[i] * br[j];
        }
        __syncthreads();
    }

    float bb[4];
    #pragma unroll
    for (int j = 0; j < 4; j++) bb[j] = bias[bn + tcol*4 + j];
    #pragma unroll
    for (int i = 0; i < 4; i++) {
        int m = bm + trow*4 + i;
        if (m < M) {
            float4 o;
            o.x = acc[i][0] + bb[0];
            o.y = acc[i][1] + bb[1];
            o.z = acc[i][2] + bb[2];
            o.w = acc[i][3] + bb[3];
            *(float4*)(C + (size_t)m*Ee + bn + tcol*4) = o;
        }
    }
}

// ---------------- per-node 5-head L=16 attention, vectorized + fused softmax ----------------
__global__ void __launch_bounds__(256) attn16(
    const float* __restrict__ Q, const float* __restrict__ K,
    const float* __restrict__ V, float* __restrict__ O)
{
    constexpr int LP = 68;
    __shared__ float sq[Ln][LP], sk[Ln][LP], sv[Ln][LP];
    __shared__ float ss[Ln][Ln + 1];
    const int n = blockIdx.x;
    const int tid = threadIdx.x;
    const size_t base = (size_t)n * Ln * Ee;

    const int ll = tid >> 4;          // 0..15
    const int lc = (tid & 15) << 2;   // 0..60

    for (int h = 0; h < NH; h++) {
        const int hc = h * HD;
        float4 q4 = *(const float4*)(Q + base + (size_t)ll*Ee + hc + lc);
        float4 k4 = *(const float4*)(K + base + (size_t)ll*Ee + hc + lc);
        float4 v4 = *(const float4*)(V + base + (size_t)ll*Ee + hc + lc);
        *(float4*)&sq[ll][lc] = q4;
        *(float4*)&sk[ll][lc] = k4;
        *(float4*)&sv[ll][lc] = v4;
        __syncthreads();

        // scores + fused softmax: thread (sl, sm); softmax across the 16-lane group
        {
            const int sl = tid >> 4, sm = tid & 15;
            float s = 0.f;
            #pragma unroll
            for (int c = 0; c < HD; c += 4) {
                float4 qv = *(const float4*)&sq[sl][c];
                float4 kv = *(const float4*)&sk[sm][c];
                s += qv.x*kv.x + qv.y*kv.y + qv.z*kv.z + qv.w*kv.w;
            }
            s *= 0.125f;  // 1/sqrt(64)
            float mx = s;
            #pragma unroll
            for (int o = 8; o > 0; o >>= 1) mx = fmaxf(mx, __shfl_xor_sync(0xffffffffu, mx, o));
            float ex = expf(s - mx);
            float sum = ex;
            #pragma unroll
            for (int o = 8; o > 0; o >>= 1) sum += __shfl_xor_sync(0xffffffffu, sum, o);
            ss[sl][sm] = ex / sum;
        }
        __syncthreads();

        // O = A @ V: thread -> (ol, 4 consecutive oc)
        {
            const int ol = tid >> 4;
            const int ocg = (tid & 15) << 2;
            float4 a = make_float4(0.f, 0.f, 0.f, 0.f);
            #pragma unroll
            for (int m = 0; m < Ln; m++) {
                float w = ss[ol][m];
                float4 vv = *(const float4*)&sv[m][ocg];
                a.x += w*vv.x; a.y += w*vv.y; a.z += w*vv.z; a.w += w*vv.w;
            }
            *(float4*)(O + base + (size_t)ol*Ee + hc + ocg) = a;
        }
        __syncthreads();
    }
}

// ---------------- final 1-head attention over 32 tokens + fused output proj + ELU ----------------
__global__ void __launch_bounds__(256) final_attn(
    const float* __restrict__ q0, const float* __restrict__ Kf,
    const float* __restrict__ Vf, const float* __restrict__ Fmat,
    const float* __restrict__ fbias, float* __restrict__ out)
{
    __shared__ float sqv[Ee];
    __shared__ float sc[32];
    __shared__ float so[Ee];
    const int n = blockIdx.x;
    const int tid = threadIdx.x;
    const int warp = tid >> 5, lane = tid & 31;
    const float scale = 0.05590169943749474f;  // 1/sqrt(320)

    if (tid < Ee/4) {
        ((float4*)sqv)[tid] = ((const float4*)(q0 + (size_t)n*Ee))[tid];
    }
    __syncthreads();

    // 32 score dot-products of length 320 (float4 path): warp w handles m = 4w..4w+3
    #pragma unroll
    for (int i = 0; i < 4; i++) {
        int m = warp*4 + i;
        const float4* kr = (const float4*)(Kf + ((size_t)n*32 + m) * Ee);
        float s = 0.f;
        #pragma unroll 1
        for (int f = lane; f < Ee/4; f += 32) {
            float4 kv = kr[f];
            float4 qv = ((const float4*)sqv)[f];
            s += qv.x*kv.x + qv.y*kv.y + qv.z*kv.z + qv.w*kv.w;
        }
        #pragma unroll
        for (int o = 16; o > 0; o >>= 1) s += __shfl_down_sync(0xffffffffu, s, o);
        if (lane == 0) sc[m] = s * scale;
    }
    __syncthreads();

    if (warp == 0) {
        float v = sc[lane];
        float mx = v;
        #pragma unroll
        for (int o = 16; o > 0; o >>= 1) mx = fmaxf(mx, __shfl_xor_sync(0xffffffffu, mx, o));
        float ex = expf(v - mx);
        float sm = ex;
        #pragma unroll
        for (int o = 16; o > 0; o >>= 1) sm += __shfl_xor_sync(0xffffffffu, sm, o);
        sc[lane] = ex / sm;
    }
    __syncthreads();

    for (int e = tid; e < Ee; e += 256) {
        const float* vr = Vf + (size_t)n*32*Ee + e;
        float a = 0.f;
        #pragma unroll
        for (int m = 0; m < 32; m++) a += sc[m] * vr[(size_t)m*Ee];
        so[e] = a;
    }
    __syncthreads();

    #pragma unroll
    for (int i = 0; i < 4; i++) {
        int j = warp*4 + i;
        if (j < OUTD) {
            float s = 0.f;
            for (int e = lane; e < Ee; e += 32) s += so[e] * Fmat[(size_t)e*OUTD + j];
            #pragma unroll
            for (int o = 16; o > 0; o >>= 1) s += __shfl_down_sync(0xffffffffu, s, o);
            if (lane == 0) {
                float x = s + fbias[j];
                out[(size_t)n*OUTD + j] = x > 0.f ? x : expm1f(x);
            }
        }
    }
}

// ---------------- host ----------------
#define GETSYM(p, s) do { void* _t; cudaGetSymbolAddress(&_t, s); p = decltype(p)(_t); } while (0)

extern "C" void kernel_launch(void* const* d_in, const int* in_sizes, int n_in,
                              void* d_out, int out_size)
{
    const float* X        = (const float*)d_in[0];
    const int*   in_idx   = (const int*)  d_in[1];
    const int*   out_idx  = (const int*)  d_in[2];
    const float* in_Wq    = (const float*)d_in[3];
    const float* in_Wk    = (const float*)d_in[4];
    const float* in_Wv    = (const float*)d_in[5];
    const float* in_qkv_w = (const float*)d_in[6];
    const float* in_qkv_b = (const float*)d_in[7];
    const float* in_o_w   = (const float*)d_in[8];
    const float* in_o_b   = (const float*)d_in[9];
    const float* out_Wq   = (const float*)d_in[10];
    const float* out_Wk   = (const float*)d_in[11];
    const float* out_Wv   = (const float*)d_in[12];
    const float* out_qkv_w= (const float*)d_in[13];
    const float* out_qkv_b= (const float*)d_in[14];
    const float* out_o_w  = (const float*)d_in[15];
    const float* out_o_b  = (const float*)d_in[16];
    const float* fin_qkv_w= (const float*)d_in[17];
    const float* fin_qkv_b= (const float*)d_in[18];
    const float* fin_o_w  = (const float*)d_in[19];
    const float* fin_o_b  = (const float*)d_in[20];
    const float* Wfin     = (const float*)d_in[21];
    float* out = (float*)d_out;

    float *Mq_in, *Mk_in, *Mv_in, *Mq_out, *Mk_out, *Mv_out;
    float *Qmat, *Kmat_in, *Kmat_out, *Vmat_in, *Vmat_out;
    float *T_in_o, *T_out_o, *T_fin_o;
    float *qbias, *kbias_in, *kbias_out, *vbias_in, *vbias_out;
    float *Fmat, *fbias, *Q, *K, *V, *Oin, *Oout, *Kf, *Vf, *q0;
    int *rows_in, *rows_out, *rows_q0;
    GETSYM(Mq_in, g_Mq_in);   GETSYM(Mk_in, g_Mk_in);   GETSYM(Mv_in, g_Mv_in);
    GETSYM(Mq_out, g_Mq_out); GETSYM(Mk_out, g_Mk_out); GETSYM(Mv_out, g_Mv_out);
    GETSYM(Qmat, g_Qmat);     GETSYM(Kmat_in, g_Kmat_in); GETSYM(Kmat_out, g_Kmat_out);
    GETSYM(Vmat_in, g_Vmat_in); GETSYM(Vmat_out, g_Vmat_out);
    GETSYM(T_in_o, g_T_in_o); GETSYM(T_out_o, g_T_out_o); GETSYM(T_fin_o, g_T_fin_o);
    GETSYM(qbias, g_qbias);   GETSYM(kbias_in, g_kbias_in); GETSYM(kbias_out, g_kbias_out);
    GETSYM(vbias_in, g_vbias_in); GETSYM(vbias_out, g_vbias_out);
    GETSYM(Fmat, g_Fmat);     GETSYM(fbias, g_fbias);
    GETSYM(Q, g_Q); GETSYM(K, g_K); GETSYM(V, g_V);
    GETSYM(Oin, g_Oin); GETSYM(Oout, g_Oout);
    GETSYM(Kf, g_Kf); GETSYM(Vf, g_Vf); GETSYM(q0, g_q0);
    GETSYM(rows_in, g_rows_in); GETSYM(rows_out, g_rows_out); GETSYM(rows_q0, g_rows_q0);

    const int CB = 256;

    // dynamic smem opt-in for the 3-stage pipelined GEMMs
    const int SMEM3 = (3*128*36 + 3*3*32*72) * 4;   // 138240
    const int SMEM2 = (3*128*36 + 3*2*32*72) * 4;   // 110592
    cudaFuncSetAttribute(gemm_tc<3>, cudaFuncAttributeMaxDynamicSharedMemorySize, SMEM3);
    cudaFuncSetAttribute(gemm_tc<2>, cudaFuncAttributeMaxDynamicSharedMemorySize, SMEM2);

    // 1) row gather tables + transposes of the three output-proj matrices
    build_rows<<<(Nn + CB - 1)/CB, CB>>>(in_idx, out_idx, rows_in, rows_out, rows_q0);
    dim3 tG(10, 10), tB(32, 8);
    transpose320<<<tG, tB>>>(in_o_w,  T_in_o);
    transpose320<<<tG, tB>>>(out_o_w, T_out_o);
    transpose320<<<tG, tB>>>(fin_o_w, T_fin_o);

    // 2+3) all 11 combined matrices in ONE batched launch: C = A @ B^T
    CombineBatch cb;
    cb.A[0] = in_Wq;   cb.B[0] = in_qkv_w;            cb.C[0] = Mq_in;
    cb.A[1] = in_Wk;   cb.B[1] = in_qkv_w + Ee*Ee;    cb.C[1] = Mk_in;
    cb.A[2] = in_Wv;   cb.B[2] = in_qkv_w + 2*Ee*Ee;  cb.C[2] = Mv_in;
    cb.A[3] = out_Wq;  cb.B[3] = out_qkv_w;           cb.C[3] = Mq_out;
    cb.A[4] = out_Wk;  cb.B[4] = out_qkv_w + Ee*Ee;   cb.C[4] = Mk_out;
    cb.A[5] = out_Wv;  cb.B[5] = out_qkv_w + 2*Ee*Ee; cb.C[5] = Mv_out;
    cb.A[6] = T_in_o;  cb.B[6] = fin_qkv_w;           cb.C[6] = Qmat;
    cb.A[7] = T_in_o;  cb.B[7] = fin_qkv_w + Ee*Ee;   cb.C[7] = Kmat_in;
    cb.A[8] = T_out_o; cb.B[8] = fin_qkv_w + Ee*Ee;   cb.C[8] = Kmat_out;
    cb.A[9] = T_in_o;  cb.B[9] = fin_qkv_w + 2*Ee*Ee; cb.C[9] = Vmat_in;
    cb.A[10]= T_out_o; cb.B[10]= fin_qkv_w + 2*Ee*Ee; cb.C[10]= Vmat_out;
    combine_batch<<<dim3(5, 5, NCOMB), CB>>>(cb);

    BiasBatch bb;
    bb.bo[0] = in_o_b;  bb.Bq[0] = fin_qkv_w;           bb.b2[0] = fin_qkv_b;          bb.out[0] = qbias;
    bb.bo[1] = in_o_b;  bb.Bq[1] = fin_qkv_w + Ee*Ee;   bb.b2[1] = fin_qkv_b + Ee;     bb.out[1] = kbias_in;
    bb.bo[2] = out_o_b; bb.Bq[2] = fin_qkv_w + Ee*Ee;   bb.b2[2] = fin_qkv_b + Ee;     bb.out[2] = kbias_out;
    bb.bo[3] = in_o_b;  bb.Bq[3] = fin_qkv_w + 2*Ee*Ee; bb.b2[3] = fin_qkv_b + 2*Ee;   bb.out[3] = vbias_in;
    bb.bo[4] = out_o_b; bb.Bq[4] = fin_qkv_w + 2*Ee*Ee; bb.b2[4] = fin_qkv_b + 2*Ee;   bb.out[4] = vbias_out;
    bias_batch<<<dim3(40, NBIAS), CB>>>(bb);

    // 4) fold final output-proj into readout: Fmat = wof.T @ W
    combine_fmat_w<<<(Ee*OUTD + 7)/8, CB>>>(T_fin_o, Wfin, Fmat);
    combine_fbias_w<<<1, CB>>>(fin_o_b, Wfin, fbias);

    const int Mfull = Nn * Ln;           // 160000 = 1250 * 128
    dim3 gemmGrid(Ee/64, Mfull/128);
    dim3 gemmGridQ0(Ee/64, (Nn + 63)/64);

    // 5) in-layer fused Q/K/V (tensor cores, one gathered-A pass), attention -> Oin
    gemm_tc<3><<<gemmGrid, 256, SMEM3>>>(X, rows_in,
        Mq_in, Mk_in, Mv_in,
        in_qkv_b, in_qkv_b + Ee, in_qkv_b + 2*Ee,
        Q, K, V, 16, 16, 0);
    attn16<<<Nn, 256>>>(Q, K, V, Oin);

    // 6) out-layer
    gemm_tc<3><<<gemmGrid, 256, SMEM3>>>(X, rows_out,
        Mq_out, Mk_out, Mv_out,
        out_qkv_b, out_qkv_b + Ee, out_qkv_b + 2*Ee,
        Q, K, V, 16, 16, 0);
    attn16<<<Nn, 256>>>(Q, K, V, Oout);

    // 7) final-layer K/V fused per source (interleaved halves: rows n*32+l, n*32+16+l)
    gemm_tc<2><<<gemmGrid, 256, SMEM2>>>(Oin, nullptr,
        Kmat_in, Vmat_in, nullptr,
        kbias_in, vbias_in, nullptr,
        Kf, Vf, nullptr, 16, 32, 0);
    gemm_tc<2><<<gemmGrid, 256, SMEM2>>>(Oout, nullptr,
        Kmat_out, Vmat_out, nullptr,
        kbias_out, vbias_out, nullptr,
        Kf, Vf, nullptr, 16, 32, 16);
    gemm320<<<gemmGridQ0, 256>>>(Oin, rows_q0, Nn, Qmat, qbias, q0);

    // 8) final attention + fused readout + ELU
    final_attn<<<Nn, 256>>>(q0, Kf, Vf, Fmat, fbias, out);
}

// round 11
// speedup vs baseline: 1.0870x; 1.0870x over previous
#include <cuda_runtime.h>
#include <math.h>
#include <stdint.h>

#define Nn 10000
#define Dn 15
#define Ln 16
#define Ee 320
#define OUTD 30
#define NH 5
#define HD 64

// ---------------- scratch (static device globals; no allocation) ----------------
__device__ float g_Mq_in[Ee*Ee], g_Mk_in[Ee*Ee], g_Mv_in[Ee*Ee];
__device__ float g_Mq_out[Ee*Ee], g_Mk_out[Ee*Ee], g_Mv_out[Ee*Ee];
__device__ float g_Qmat[Ee*Ee], g_Kmat_in[Ee*Ee], g_Kmat_out[Ee*Ee];
__device__ float g_Vmat_in[Ee*Ee], g_Vmat_out[Ee*Ee];
__device__ float g_T_in_o[Ee*Ee], g_T_out_o[Ee*Ee], g_T_fin_o[Ee*Ee];
__device__ float g_qbias[Ee], g_kbias_in[Ee], g_kbias_out[Ee], g_vbias_in[Ee], g_vbias_out[Ee];
__device__ float g_Fmat[Ee*OUTD], g_fbias[OUTD];
__device__ int   g_rows_in[Nn*Ln], g_rows_out[Nn*Ln], g_rows_q0[Nn];
__device__ float g_Q[(size_t)Nn*Ln*Ee],  g_K[(size_t)Nn*Ln*Ee],  g_V[(size_t)Nn*Ln*Ee];
__device__ float g_Q2[(size_t)Nn*Ln*Ee], g_K2[(size_t)Nn*Ln*Ee], g_V2[(size_t)Nn*Ln*Ee];
__device__ float g_Oin[(size_t)Nn*Ln*Ee], g_Oout[(size_t)Nn*Ln*Ee];
__device__ float g_Kf[(size_t)Nn*2*Ln*Ee], g_Vf[(size_t)Nn*2*Ln*Ee];
__device__ float g_q0[(size_t)Nn*Ee];

// ---------------- helpers ----------------
__device__ __forceinline__ void mma_tf32(float* d, const uint32_t* a, uint32_t b0, uint32_t b1) {
    asm volatile(
        "mma.sync.aligned.m16n8k8.row.col.f32.tf32.tf32.f32 "
        "{%0,%1,%2,%3}, {%4,%5,%6,%7}, {%8,%9}, {%0,%1,%2,%3};"
        : "+f"(d[0]), "+f"(d[1]), "+f"(d[2]), "+f"(d[3])
        : "r"(a[0]), "r"(a[1]), "r"(a[2]), "r"(a[3]), "r"(b0), "r"(b1));
}

__device__ __forceinline__ void cp_async16(void* smem_dst, const void* gmem_src) {
    uint32_t d = (uint32_t)__cvta_generic_to_shared(smem_dst);
    asm volatile("cp.async.cg.shared.global [%0], [%1], 16;" :: "r"(d), "l"(gmem_src));
}
__device__ __forceinline__ void cp_commit() {
    asm volatile("cp.async.commit_group;" ::: "memory");
}

// ---------------- precompute kernels ----------------

__global__ void transpose320(const float* __restrict__ in, float* __restrict__ out) {
    __shared__ float tile[32][33];
    int bx = blockIdx.x * 32, by = blockIdx.y * 32;
    int x = bx + threadIdx.x;
    #pragma unroll
    for (int i = 0; i < 32; i += 8) {
        int y = by + threadIdx.y + i;
        tile[threadIdx.y + i][threadIdx.x] = in[(size_t)y*Ee + x];
    }
    __syncthreads();
    x = by + threadIdx.x;
    #pragma unroll
    for (int i = 0; i < 32; i += 8) {
        int y = bx + threadIdx.y + i;
        out[(size_t)y*Ee + x] = tile[threadIdx.x][threadIdx.y + i];
    }
}

#define NCOMB 11
struct CombineBatch {
    const float* A[NCOMB];
    const float* B[NCOMB];
    float*       C[NCOMB];
};
__global__ void __launch_bounds__(256) combine_batch(CombineBatch p) {
    const float* __restrict__ A = p.A[blockIdx.z];
    const float* __restrict__ B = p.B[blockIdx.z];
    float* __restrict__ C = p.C[blockIdx.z];
    constexpr int BK = 16;
    __shared__ float As[BK][64];
    __shared__ float Bs[BK][64];
    const int tid = threadIdx.x;
    const int bm = blockIdx.y * 64;
    const int bn = blockIdx.x * 64;
    const int tcol = tid & 15, trow = tid >> 4;
    const int aRow = tid >> 2, aCol = (tid & 3) << 2;

    float acc[4][4];
    #pragma unroll
    for (int i = 0; i < 4; i++)
        #pragma unroll
        for (int j = 0; j < 4; j++) acc[i][j] = 0.f;

    for (int k0 = 0; k0 < Ee; k0 += BK) {
        float4 a4 = *(const float4*)(A + (size_t)(bm + aRow)*Ee + k0 + aCol);
        float4 b4 = *(const float4*)(B + (size_t)(bn + aRow)*Ee + k0 + aCol);
        As[aCol+0][aRow] = a4.x; As[aCol+1][aRow] = a4.y;
        As[aCol+2][aRow] = a4.z; As[aCol+3][aRow] = a4.w;
        Bs[aCol+0][aRow] = b4.x; Bs[aCol+1][aRow] = b4.y;
        Bs[aCol+2][aRow] = b4.z; Bs[aCol+3][aRow] = b4.w;
        __syncthreads();
        #pragma unroll
        for (int kk = 0; kk < BK; kk++) {
            float ar[4], br[4];
            #pragma unroll
            for (int i = 0; i < 4; i++) ar[i] = As[kk][trow*4 + i];
            #pragma unroll
            for (int j = 0; j < 4; j++) br[j] = Bs[kk][tcol*4 + j];
            #pragma unroll
            for (int i = 0; i < 4; i++)
                #pragma unroll
                for (int j = 0; j < 4; j++)
                    acc[i][j] += ar[i] * br[j];
        }
        __syncthreads();
    }
    #pragma unroll
    for (int i = 0; i < 4; i++)
        #pragma unroll
        for (int j = 0; j < 4; j++)
            C[(size_t)(bm + trow*4 + i)*Ee + bn + tcol*4 + j] = acc[i][j];
}

#define NBIAS 5
struct BiasBatch {
    const float* bo[NBIAS];
    const float* Bq[NBIAS];
    const float* b2[NBIAS];
    float*       out[NBIAS];
};
__global__ void __launch_bounds__(256) bias_batch(BiasBatch p) {
    int task = blockIdx.y;
    const float* __restrict__ bo = p.bo[task];
    const float* __restrict__ Bq = p.Bq[task];
    int j = (blockIdx.x * 256 + threadIdx.x) >> 5;
    int lane = threadIdx.x & 31;
    if (j >= Ee) return;
    const float* br = Bq + (size_t)j*Ee;
    float s = 0.f;
    #pragma unroll
    for (int e = lane, i = 0; i < Ee/32; e += 32, i++) s += bo[e] * br[e];
    #pragma unroll
    for (int off = 16; off > 0; off >>= 1) s += __shfl_down_sync(0xffffffffu, s, off);
    if (lane == 0) p.out[task][j] = s + p.b2[task][j];
}

__global__ void combine_fmat_w(const float* __restrict__ fowT, const float* __restrict__ W,
                               float* __restrict__ out) {
    int o = (blockIdx.x * 256 + threadIdx.x) >> 5;
    int lane = threadIdx.x & 31;
    if (o >= Ee*OUTD) return;
    int e = o / OUTD, j = o % OUTD;
    const float* fr = fowT + (size_t)e*Ee;
    float s = 0.f;
    #pragma unroll
    for (int t = lane, i = 0; i < Ee/32; t += 32, i++) s += fr[t] * W[(size_t)t*OUTD + j];
    #pragma unroll
    for (int off = 16; off > 0; off >>= 1) s += __shfl_down_sync(0xffffffffu, s, off);
    if (lane == 0) out[o] = s;
}

__global__ void combine_fbias_w(const float* __restrict__ fob, const float* __restrict__ W,
                                float* __restrict__ out) {
    int warp = threadIdx.x >> 5, lane = threadIdx.x & 31;
    for (int j = warp; j < OUTD; j += 8) {
        float s = 0.f;
        #pragma unroll
        for (int t = lane, i = 0; i < Ee/32; t += 32, i++) s += fob[t] * W[(size_t)t*OUTD + j];
        #pragma unroll
        for (int off = 16; off > 0; off >>= 1) s += __shfl_down_sync(0xffffffffu, s, off);
        if (lane == 0) out[j] = s;
    }
}

__global__ void build_rows(const int* __restrict__ in_idx, const int* __restrict__ out_idx,
                           int* __restrict__ rin, int* __restrict__ rout, int* __restrict__ rq0) {
    int n = blockIdx.x * blockDim.x + threadIdx.x;
    if (n >= Nn) return;
    rin[n*Ln] = n;
    rout[n*Ln] = n;
    rq0[n] = n*Ln;
    #pragma unroll
    for (int d = 0; d < Dn; d++) {
        rin[n*Ln + 1 + d]  = in_idx[n*Dn + d];
        rout[n*Ln + 1 + d] = out_idx[n*Dn + d];
    }
}

// ---------------- dual tensor-core multi-B GEMM (R7 2-stage pipeline, grid.z=2) ----------------
// tf32 HMMA (fp32 bits fed directly; HW truncates), fp32 accumulate.
// BM=128, BN=64, BK=32, 2 stages in dynamic smem. M % 128 == 0. blockIdx.z selects task.
struct DualArgs {
    const float* A[2];
    const int*   rows[2];
    const float* B[2][3];
    const float* bias[2][3];
    float*       C[2][3];
    int out_grp, out_str;
    int out_off[2];
};

template<int NMAT>
__global__ void __launch_bounds__(256) gemm_tc_dual(DualArgs p)
{
    constexpr int BM = 128, BN = 64, BK = 32;
    constexpr int ASTR = 36;
    constexpr int BSTR = 72;
    constexpr int NT = Ee / BK;  // 10
    extern __shared__ float smp[];
    float* AsBase = smp;                      // [2][BM*ASTR]
    float* BsBase = smp + 2*BM*ASTR;          // [2][NMAT][BK*BSTR]

    const int z = blockIdx.z;
    const float* __restrict__ A = p.A[z];
    const int* __restrict__ rows = p.rows[z];
    const int out_grp = p.out_grp, out_str = p.out_str, out_off = p.out_off[z];

    const int tid = threadIdx.x;
    const int bm = blockIdx.y * BM;
    const int bn = blockIdx.x * BN;
    const int warpId = tid >> 5, lane = tid & 31;
    const int wm = (warpId & 3) * 32;
    const int wn = (warpId >> 2) * 32;
    const int g = lane >> 2, t = lane & 3;

    const float* Bp[NMAT]; const float* biasp[NMAT]; float* Cp[NMAT];
    #pragma unroll
    for (int q = 0; q < NMAT; q++) { Bp[q] = p.B[z][q]; biasp[q] = p.bias[z][q]; Cp[q] = p.C[z][q]; }

    float acc[NMAT][2][4][4];
    #pragma unroll
    for (int q = 0; q < NMAT; q++)
        #pragma unroll
        for (int mi = 0; mi < 2; mi++)
            #pragma unroll
            for (int ni = 0; ni < 4; ni++)
                #pragma unroll
                for (int v = 0; v < 4; v++) acc[q][mi][ni][v] = 0.f;

    const int aRow = tid >> 3;
    const int aCol = (tid & 7) * 4;
    size_t gA[4];
    #pragma unroll
    for (int i = 0; i < 4; i++) {
        int m = bm + aRow + i*32;
        gA[i] = (size_t)(rows ? rows[m] : m) * Ee;
    }
    const int bRow = tid >> 4;
    const int bCol = (tid & 15) * 4;

    auto issue = [&](int kt, int st) {
        float* As = AsBase + st*BM*ASTR;
        #pragma unroll
        for (int i = 0; i < 4; i++)
            cp_async16(&As[(aRow + i*32)*ASTR + aCol], A + gA[i] + kt*BK + aCol);
        #pragma unroll
        for (int q = 0; q < NMAT; q++) {
            float* Bs = BsBase + (st*NMAT + q)*BK*BSTR;
            #pragma unroll
            for (int i = 0; i < 2; i++) {
                int kr = bRow + i*16;
                cp_async16(&Bs[kr*BSTR + bCol], Bp[q] + (size_t)(kt*BK + kr)*Ee + bn + bCol);
            }
        }
    };

    auto compute = [&](int st) {
        const float* As = AsBase + st*BM*ASTR;
        #pragma unroll
        for (int kk = 0; kk < BK; kk += 8) {
            uint32_t afr[2][4];
            #pragma unroll
            for (int mi = 0; mi < 2; mi++) {
                int r0 = wm + mi*16 + g;
                afr[mi][0] = __float_as_uint(As[(r0    )*ASTR + kk + t    ]);
                afr[mi][1] = __float_as_uint(As[(r0 + 8)*ASTR + kk + t    ]);
                afr[mi][2] = __float_as_uint(As[(r0    )*ASTR + kk + t + 4]);
                afr[mi][3] = __float_as_uint(As[(r0 + 8)*ASTR + kk + t + 4]);
            }
            #pragma unroll
            for (int q = 0; q < NMAT; q++) {
                const float* Bs = BsBase + (st*NMAT + q)*BK*BSTR;
                #pragma unroll
                for (int ni = 0; ni < 4; ni++) {
                    int nc = wn + ni*8 + g;
                    uint32_t b0 = __float_as_uint(Bs[(kk + t    )*BSTR + nc]);
                    uint32_t b1 = __float_as_uint(Bs[(kk + t + 4)*BSTR + nc]);
                    #pragma unroll
                    for (int mi = 0; mi < 2; mi++)
                        mma_tf32(acc[q][mi][ni], afr[mi], b0, b1);
                }
            }
        }
    };

    // R7 pipeline: 2-stage double buffer, two barriers per iteration.
    issue(0, 0);
    cp_commit();

    #pragma unroll 1
    for (int kt = 0; kt < NT; kt++) {
        int st = kt & 1;
        if (kt + 1 < NT) {
            issue(kt + 1, st ^ 1);
            cp_commit();
            asm volatile("cp.async.wait_group 1;" ::: "memory");
        } else {
            asm volatile("cp.async.wait_group 0;" ::: "memory");
        }
        __syncthreads();
        compute(st);
        __syncthreads();
    }

    // epilogue
    #pragma unroll
    for (int q = 0; q < NMAT; q++) {
        #pragma unroll
        for (int ni = 0; ni < 4; ni++) {
            int n = bn + wn + ni*8 + 2*t;
            float bb0 = biasp[q][n], bb1 = biasp[q][n+1];
            #pragma unroll
            for (int mi = 0; mi < 2; mi++) {
                int m0 = bm + wm + mi*16 + g;
                int m1 = m0 + 8;
                int cr0 = (m0 / out_grp) * out_str + (m0 % out_grp) + out_off;
                int cr1 = (m1 / out_grp) * out_str + (m1 % out_grp) + out_off;
                float2 v0, v1;
                v0.x = acc[q][mi][ni][0] + bb0; v0.y = acc[q][mi][ni][1] + bb1;
                v1.x = acc[q][mi][ni][2] + bb0; v1.y = acc[q][mi][ni][3] + bb1;
                *(float2*)(Cp[q] + (size_t)cr0*Ee + n) = v0;
                *(float2*)(Cp[q] + (size_t)cr1*Ee + n) = v1;
            }
        }
    }
}

// ---------------- single-B SIMT GEMM with M guard (q0: M = 10000, fp32 exact) ----------------
__global__ void __launch_bounds__(256) gemm320(
    const float* __restrict__ A, const int* __restrict__ rows, int M,
    const float* __restrict__ B, const float* __restrict__ bias,
    float* __restrict__ C)
{
    constexpr int BM = 64, BN = 64, BK = 16;
    __shared__ float As[BK][BM];
    __shared__ float Bs[BK][BN];
    const int tid = threadIdx.x;
    const int bm = blockIdx.y * BM;
    const int bn = blockIdx.x * BN;
    const int tcol = tid & 15;
    const int trow = tid >> 4;

    float acc[4][4];
    #pragma unroll
    for (int i = 0; i < 4; i++)
        #pragma unroll
        for (int j = 0; j < 4; j++) acc[i][j] = 0.f;

    const int aRow = tid >> 2;
    const int aCol = (tid & 3) << 2;
    int r = bm + aRow; if (r >= M) r = M - 1;
    const size_t ga = (size_t)(rows ? rows[r] : r) * Ee;
    const int bRow = tid >> 4;
    const int bCol = (tid & 15) << 2;

    for (int k0 = 0; k0 < Ee; k0 += BK) {
        float4 a4 = *(const float4*)(A + ga + k0 + aCol);
        float4 b4 = *(const float4*)(B + (size_t)(k0 + bRow)*Ee + bn + bCol);
        As[aCol+0][aRow] = a4.x; As[aCol+1][aRow] = a4.y;
        As[aCol+2][aRow] = a4.z; As[aCol+3][aRow] = a4.w;
        *(float4*)&Bs[bRow][bCol] = b4;
        __syncthreads();

        #pragma unroll
        for (int kk = 0; kk < BK; kk++) {
            float ar[4], br[4];
            #pragma unroll
            for (int i = 0; i < 4; i++) ar[i] = As[kk][trow*4 + i];
            #pragma unroll
            for (int j = 0; j < 4; j++) br[j] = Bs[kk][tcol*4 + j];
            #pragma unroll
            for (int i = 0; i < 4; i++)
                #pragma unroll
                for (int j = 0; j < 4; j++)
                    acc[i][j] += ar[i] * br[j];
        }
        __syncthreads();
    }

    float bb[4];
    #pragma unroll
    for (int j = 0; j < 4; j++) bb[j] = bias[bn + tcol*4 + j];
    #pragma unroll
    for (int i = 0; i < 4; i++) {
        int m = bm + trow*4 + i;
        if (m < M) {
            float4 o;
            o.x = acc[i][0] + bb[0];
            o.y = acc[i][1] + bb[1];
            o.z = acc[i][2] + bb[2];
            o.w = acc[i][3] + bb[3];
            *(float4*)(C + (size_t)m*Ee + bn + tcol*4) = o;
        }
    }
}

// ---------------- merged per-node 5-head attention: blocks [0,Nn)->in, [Nn,2Nn)->out ----------------
__global__ void __launch_bounds__(256) attn16_dual(
    const float* __restrict__ Q1, const float* __restrict__ K1,
    const float* __restrict__ V1, float* __restrict__ O1,
    const float* __restrict__ Q2, const float* __restrict__ K2,
    const float* __restrict__ V2, float* __restrict__ O2)
{
    constexpr int LP = 68;
    __shared__ float sq[Ln][LP], sk[Ln][LP], sv[Ln][LP];
    __shared__ float ss[Ln][Ln + 1];
    int n = blockIdx.x;
    const float *Q, *K, *V; float* O;
    if (n < Nn) { Q = Q1; K = K1; V = V1; O = O1; }
    else        { Q = Q2; K = K2; V = V2; O = O2; n -= Nn; }
    const int tid = threadIdx.x;
    const size_t base = (size_t)n * Ln * Ee;

    const int ll = tid >> 4;          // 0..15
    const int lc = (tid & 15) << 2;   // 0..60

    for (int h = 0; h < NH; h++) {
        const int hc = h * HD;
        float4 q4 = *(const float4*)(Q + base + (size_t)ll*Ee + hc + lc);
        float4 k4 = *(const float4*)(K + base + (size_t)ll*Ee + hc + lc);
        float4 v4 = *(const float4*)(V + base + (size_t)ll*Ee + hc + lc);
        *(float4*)&sq[ll][lc] = q4;
        *(float4*)&sk[ll][lc] = k4;
        *(float4*)&sv[ll][lc] = v4;
        __syncthreads();

        // scores + fused softmax across the 16-lane group
        {
            const int sl = tid >> 4, sm = tid & 15;
            float s = 0.f;
            #pragma unroll
            for (int c = 0; c < HD; c += 4) {
                float4 qv = *(const float4*)&sq[sl][c];
                float4 kv = *(const float4*)&sk[sm][c];
                s += qv.x*kv.x + qv.y*kv.y + qv.z*kv.z + qv.w*kv.w;
            }
            s *= 0.125f;  // 1/sqrt(64)
            float mx = s;
            #pragma unroll
            for (int o = 8; o > 0; o >>= 1) mx = fmaxf(mx, __shfl_xor_sync(0xffffffffu, mx, o));
            float ex = expf(s - mx);
            float sum = ex;
            #pragma unroll
            for (int o = 8; o > 0; o >>= 1) sum += __shfl_xor_sync(0xffffffffu, sum, o);
            ss[sl][sm] = ex / sum;
        }
        __syncthreads();

        // O = A @ V
        {
            const int ol = tid >> 4;
            const int ocg = (tid & 15) << 2;
            float4 a = make_float4(0.f, 0.f, 0.f, 0.f);
            #pragma unroll
            for (int m = 0; m < Ln; m++) {
                float w = ss[ol][m];
                float4 vv = *(const float4*)&sv[m][ocg];
                a.x += w*vv.x; a.y += w*vv.y; a.z += w*vv.z; a.w += w*vv.w;
            }
            *(float4*)(O + base + (size_t)ol*Ee + hc + ocg) = a;
        }
        __syncthreads();
    }
}

// ---------------- final 1-head attention over 32 tokens + fused output proj + ELU ----------------
__global__ void __launch_bounds__(256) final_attn(
    const float* __restrict__ q0, const float* __restrict__ Kf,
    const float* __restrict__ Vf, const float* __restrict__ Fmat,
    const float* __restrict__ fbias, float* __restrict__ out)
{
    __shared__ float sqv[Ee];
    __shared__ float sc[32];
    __shared__ float so[Ee];
    const int n = blockIdx.x;
    const int tid = threadIdx.x;
    const int warp = tid >> 5, lane = tid & 31;
    const float scale = 0.05590169943749474f;  // 1/sqrt(320)

    if (tid < Ee/4) {
        ((float4*)sqv)[tid] = ((const float4*)(q0 + (size_t)n*Ee))[tid];
    }
    __syncthreads();

    #pragma unroll
    for (int i = 0; i < 4; i++) {
        int m = warp*4 + i;
        const float4* kr = (const float4*)(Kf + ((size_t)n*32 + m) * Ee);
        float s = 0.f;
        #pragma unroll 1
        for (int f = lane; f < Ee/4; f += 32) {
            float4 kv = kr[f];
            float4 qv = ((const float4*)sqv)[f];
            s += qv.x*kv.x + qv.y*kv.y + qv.z*kv.z + qv.w*kv.w;
        }
        #pragma unroll
        for (int o = 16; o > 0; o >>= 1) s += __shfl_down_sync(0xffffffffu, s, o);
        if (lane == 0) sc[m] = s * scale;
    }
    __syncthreads();

    if (warp == 0) {
        float v = sc[lane];
        float mx = v;
        #pragma unroll
        for (int o = 16; o > 0; o >>= 1) mx = fmaxf(mx, __shfl_xor_sync(0xffffffffu, mx, o));
        float ex = expf(v - mx);
        float sm = ex;
        #pragma unroll
        for (int o = 16; o > 0; o >>= 1) sm += __shfl_xor_sync(0xffffffffu, sm, o);
        sc[lane] = ex / sm;
    }
    __syncthreads();

    for (int e = tid; e < Ee; e += 256) {
        const float* vr = Vf + (size_t)n*32*Ee + e;
        float a = 0.f;
        #pragma unroll
        for (int m = 0; m < 32; m++) a += sc[m] * vr[(size_t)m*Ee];
        so[e] = a;
    }
    __syncthreads();

    #pragma unroll
    for (int i = 0; i < 4; i++) {
        int j = warp*4 + i;
        if (j < OUTD) {
            float s = 0.f;
            for (int e = lane; e < Ee; e += 32) s += so[e] * Fmat[(size_t)e*OUTD + j];
            #pragma unroll
            for (int o = 16; o > 0; o >>= 1) s += __shfl_down_sync(0xffffffffu, s, o);
            if (lane == 0) {
                float x = s + fbias[j];
                out[(size_t)n*OUTD + j] = x > 0.f ? x : expm1f(x);
            }
        }
    }
}

// ---------------- host ----------------
#define GETSYM(p, s) do { void* _t; cudaGetSymbolAddress(&_t, s); p = decltype(p)(_t); } while (0)

extern "C" void kernel_launch(void* const* d_in, const int* in_sizes, int n_in,
                              void* d_out, int out_size)
{
    const float* X        = (const float*)d_in[0];
    const int*   in_idx   = (const int*)  d_in[1];
    const int*   out_idx  = (const int*)  d_in[2];
    const float* in_Wq    = (const float*)d_in[3];
    const float* in_Wk    = (const float*)d_in[4];
    const float* in_Wv    = (const float*)d_in[5];
    const float* in_qkv_w = (const float*)d_in[6];
    const float* in_qkv_b = (const float*)d_in[7];
    const float* in_o_w   = (const float*)d_in[8];
    const float* in_o_b   = (const float*)d_in[9];
    const float* out_Wq   = (const float*)d_in[10];
    const float* out_Wk   = (const float*)d_in[11];
    const float* out_Wv   = (const float*)d_in[12];
    const float* out_qkv_w= (const float*)d_in[13];
    const float* out_qkv_b= (const float*)d_in[14];
    const float* out_o_w  = (const float*)d_in[15];
    const float* out_o_b  = (const float*)d_in[16];
    const float* fin_qkv_w= (const float*)d_in[17];
    const float* fin_qkv_b= (const float*)d_in[18];
    const float* fin_o_w  = (const float*)d_in[19];
    const float* fin_o_b  = (const float*)d_in[20];
    const float* Wfin     = (const float*)d_in[21];
    float* out = (float*)d_out;

    float *Mq_in, *Mk_in, *Mv_in, *Mq_out, *Mk_out, *Mv_out;
    float *Qmat, *Kmat_in, *Kmat_out, *Vmat_in, *Vmat_out;
    float *T_in_o, *T_out_o, *T_fin_o;
    float *qbias, *kbias_in, *kbias_out, *vbias_in, *vbias_out;
    float *Fmat, *fbias, *Q, *K, *V, *Q2, *K2, *V2, *Oin, *Oout, *Kf, *Vf, *q0;
    int *rows_in, *rows_out, *rows_q0;
    GETSYM(Mq_in, g_Mq_in);   GETSYM(Mk_in, g_Mk_in);   GETSYM(Mv_in, g_Mv_in);
    GETSYM(Mq_out, g_Mq_out); GETSYM(Mk_out, g_Mk_out); GETSYM(Mv_out, g_Mv_out);
    GETSYM(Qmat, g_Qmat);     GETSYM(Kmat_in, g_Kmat_in); GETSYM(Kmat_out, g_Kmat_out);
    GETSYM(Vmat_in, g_Vmat_in); GETSYM(Vmat_out, g_Vmat_out);
    GETSYM(T_in_o, g_T_in_o); GETSYM(T_out_o, g_T_out_o); GETSYM(T_fin_o, g_T_fin_o);
    GETSYM(qbias, g_qbias);   GETSYM(kbias_in, g_kbias_in); GETSYM(kbias_out, g_kbias_out);
    GETSYM(vbias_in, g_vbias_in); GETSYM(vbias_out, g_vbias_out);
    GETSYM(Fmat, g_Fmat);     GETSYM(fbias, g_fbias);
    GETSYM(Q, g_Q); GETSYM(K, g_K); GETSYM(V, g_V);
    GETSYM(Q2, g_Q2); GETSYM(K2, g_K2); GETSYM(V2, g_V2);
    GETSYM(Oin, g_Oin); GETSYM(Oout, g_Oout);
    GETSYM(Kf, g_Kf); GETSYM(Vf, g_Vf); GETSYM(q0, g_q0);
    GETSYM(rows_in, g_rows_in); GETSYM(rows_out, g_rows_out); GETSYM(rows_q0, g_rows_q0);

    const int CB = 256;

    // dynamic smem opt-in for the 2-stage pipelined GEMMs
    const int SMEM3 = (2*128*36 + 2*3*32*72) * 4;   // 92160
    const int SMEM2 = (2*128*36 + 2*2*32*72) * 4;   // 73728
    cudaFuncSetAttribute(gemm_tc_dual<3>, cudaFuncAttributeMaxDynamicSharedMemorySize, SMEM3);
    cudaFuncSetAttribute(gemm_tc_dual<2>, cudaFuncAttributeMaxDynamicSharedMemorySize, SMEM2);

    // 1) row gather tables + transposes of the three output-proj matrices
    build_rows<<<(Nn + CB - 1)/CB, CB>>>(in_idx, out_idx, rows_in, rows_out, rows_q0);
    dim3 tG(10, 10), tB(32, 8);
    transpose320<<<tG, tB>>>(in_o_w,  T_in_o);
    transpose320<<<tG, tB>>>(out_o_w, T_out_o);
    transpose320<<<tG, tB>>>(fin_o_w, T_fin_o);

    // 2+3) all 11 combined matrices in ONE batched launch: C = A @ B^T
    CombineBatch cb;
    cb.A[0] = in_Wq;   cb.B[0] = in_qkv_w;            cb.C[0] = Mq_in;
    cb.A[1] = in_Wk;   cb.B[1] = in_qkv_w + Ee*Ee;    cb.C[1] = Mk_in;
    cb.A[2] = in_Wv;   cb.B[2] = in_qkv_w + 2*Ee*Ee;  cb.C[2] = Mv_in;
    cb.A[3] = out_Wq;  cb.B[3] = out_qkv_w;           cb.C[3] = Mq_out;
    cb.A[4] = out_Wk;  cb.B[4] = out_qkv_w + Ee*Ee;   cb.C[4] = Mk_out;
    cb.A[5] = out_Wv;  cb.B[5] = out_qkv_w + 2*Ee*Ee; cb.C[5] = Mv_out;
    cb.A[6] = T_in_o;  cb.B[6] = fin_qkv_w;           cb.C[6] = Qmat;
    cb.A[7] = T_in_o;  cb.B[7] = fin_qkv_w + Ee*Ee;   cb.C[7] = Kmat_in;
    cb.A[8] = T_out_o; cb.B[8] = fin_qkv_w + Ee*Ee;   cb.C[8] = Kmat_out;
    cb.A[9] = T_in_o;  cb.B[9] = fin_qkv_w + 2*Ee*Ee; cb.C[9] = Vmat_in;
    cb.A[10]= T_out_o; cb.B[10]= fin_qkv_w + 2*Ee*Ee; cb.C[10]= Vmat_out;
    combine_batch<<<dim3(5, 5, NCOMB), CB>>>(cb);

    BiasBatch bb;
    bb.bo[0] = in_o_b;  bb.Bq[0] = fin_qkv_w;           bb.b2[0] = fin_qkv_b;          bb.out[0] = qbias;
    bb.bo[1] = in_o_b;  bb.Bq[1] = fin_qkv_w + Ee*Ee;   bb.b2[1] = fin_qkv_b + Ee;     bb.out[1] = kbias_in;
    bb.bo[2] = out_o_b; bb.Bq[2] = fin_qkv_w + Ee*Ee;   bb.b2[2] = fin_qkv_b + Ee;     bb.out[2] = kbias_out;
    bb.bo[3] = in_o_b;  bb.Bq[3] = fin_qkv_w + 2*Ee*Ee; bb.b2[3] = fin_qkv_b + 2*Ee;   bb.out[3] = vbias_in;
    bb.bo[4] = out_o_b; bb.Bq[4] = fin_qkv_w + 2*Ee*Ee; bb.b2[4] = fin_qkv_b + 2*Ee;   bb.out[4] = vbias_out;
    bias_batch<<<dim3(40, NBIAS), CB>>>(bb);

    // 4) fold final output-proj into readout: Fmat = wof.T @ W
    combine_fmat_w<<<(Ee*OUTD + 7)/8, CB>>>(T_fin_o, Wfin, Fmat);
    combine_fbias_w<<<1, CB>>>(fin_o_b, Wfin, fbias);

    const int Mfull = Nn * Ln;           // 160000 = 1250 * 128

    // 5+6) BOTH layers' Q/K/V in one dual launch, then both attentions in one launch
    DualArgs d3;
    d3.A[0] = X;  d3.A[1] = X;
    d3.rows[0] = rows_in;  d3.rows[1] = rows_out;
    d3.B[0][0] = Mq_in;  d3.B[0][1] = Mk_in;  d3.B[0][2] = Mv_in;
    d3.B[1][0] = Mq_out; d3.B[1][1] = Mk_out; d3.B[1][2] = Mv_out;
    d3.bias[0][0] = in_qkv_b;  d3.bias[0][1] = in_qkv_b + Ee;  d3.bias[0][2] = in_qkv_b + 2*Ee;
    d3.bias[1][0] = out_qkv_b; d3.bias[1][1] = out_qkv_b + Ee; d3.bias[1][2] = out_qkv_b + 2*Ee;
    d3.C[0][0] = Q;  d3.C[0][1] = K;  d3.C[0][2] = V;
    d3.C[1][0] = Q2; d3.C[1][1] = K2; d3.C[1][2] = V2;
    d3.out_grp = 16; d3.out_str = 16; d3.out_off[0] = 0; d3.out_off[1] = 0;
    gemm_tc_dual<3><<<dim3(Ee/64, Mfull/128, 2), 256, SMEM3>>>(d3);

    attn16_dual<<<2*Nn, 256>>>(Q, K, V, Oin, Q2, K2, V2, Oout);

    // 7) final-layer K/V: both sources in one dual launch (interleaved halves)
    DualArgs d2;
    d2.A[0] = Oin;  d2.A[1] = Oout;
    d2.rows[0] = nullptr; d2.rows[1] = nullptr;
    d2.B[0][0] = Kmat_in;  d2.B[0][1] = Vmat_in;  d2.B[0][2] = nullptr;
    d2.B[1][0] = Kmat_out; d2.B[1][1] = Vmat_out; d2.B[1][2] = nullptr;
    d2.bias[0][0] = kbias_in;  d2.bias[0][1] = vbias_in;  d2.bias[0][2] = nullptr;
    d2.bias[1][0] = kbias_out; d2.bias[1][1] = vbias_out; d2.bias[1][2] = nullptr;
    d2.C[0][0] = Kf; d2.C[0][1] = Vf; d2.C[0][2] = nullptr;
    d2.C[1][0] = Kf; d2.C[1][1] = Vf; d2.C[1][2] = nullptr;
    d2.out_grp = 16; d2.out_str = 32; d2.out_off[0] = 0; d2.out_off[1] = 16;
    gemm_tc_dual<2><<<dim3(Ee/64, Mfull/128, 2), 256, SMEM2>>>(d2);

    gemm320<<<dim3(Ee/64, (Nn + 63)/64), 256>>>(Oin, rows_q0, Nn, Qmat, qbias, q0);

    // 8) final attention + fused readout + ELU
    final_attn<<<Nn, 256>>>(q0, Kf, Vf, Fmat, fbias, out);
}

// round 13
// speedup vs baseline: 1.1036x; 1.0153x over previous
#include <cuda_runtime.h>
#include <math.h>
#include <stdint.h>

#define Nn 10000
#define Dn 15
#define Ln 16
#define Ee 320
#define OUTD 30
#define NH 5
#define HD 64

// ---------------- scratch (static device globals; no allocation) ----------------
__device__ float g_Mq_in[Ee*Ee], g_Mk_in[Ee*Ee], g_Mv_in[Ee*Ee];
__device__ float g_Mq_out[Ee*Ee], g_Mk_out[Ee*Ee], g_Mv_out[Ee*Ee];
__device__ float g_Qmat[Ee*Ee], g_Kmat_in[Ee*Ee], g_Kmat_out[Ee*Ee];
__device__ float g_Vmat_in[Ee*Ee], g_Vmat_out[Ee*Ee];
__device__ float g_T_in_o[Ee*Ee], g_T_out_o[Ee*Ee], g_T_fin_o[Ee*Ee];
__device__ float g_qbias[Ee], g_kbias_in[Ee], g_kbias_out[Ee], g_vbias_in[Ee], g_vbias_out[Ee];
__device__ float g_Fmat[Ee*OUTD], g_fbias[OUTD];
__device__ int   g_rows_in[Nn*Ln], g_rows_out[Nn*Ln], g_rows_q0[Nn];
__device__ float g_Q[(size_t)Nn*Ln*Ee],  g_K[(size_t)Nn*Ln*Ee],  g_V[(size_t)Nn*Ln*Ee];
__device__ float g_Q2[(size_t)Nn*Ln*Ee], g_K2[(size_t)Nn*Ln*Ee], g_V2[(size_t)Nn*Ln*Ee];
__device__ float g_Oin[(size_t)Nn*Ln*Ee], g_Oout[(size_t)Nn*Ln*Ee];
__device__ float g_Kf[(size_t)Nn*2*Ln*Ee], g_Vf[(size_t)Nn*2*Ln*Ee];
__device__ float g_q0[(size_t)Nn*Ee];

// ---------------- helpers ----------------
__device__ __forceinline__ void mma_tf32(float* d, const uint32_t* a, uint32_t b0, uint32_t b1) {
    asm volatile(
        "mma.sync.aligned.m16n8k8.row.col.f32.tf32.tf32.f32 "
        "{%0,%1,%2,%3}, {%4,%5,%6,%7}, {%8,%9}, {%0,%1,%2,%3};"
        : "+f"(d[0]), "+f"(d[1]), "+f"(d[2]), "+f"(d[3])
        : "r"(a[0]), "r"(a[1]), "r"(a[2]), "r"(a[3]), "r"(b0), "r"(b1));
}

__device__ __forceinline__ void cp_async16(void* smem_dst, const void* gmem_src) {
    uint32_t d = (uint32_t)__cvta_generic_to_shared(smem_dst);
    asm volatile("cp.async.cg.shared.global [%0], [%1], 16;" :: "r"(d), "l"(gmem_src));
}
__device__ __forceinline__ void cp_commit() {
    asm volatile("cp.async.commit_group;" ::: "memory");
}

// Permuted (MMA-fragment-order) address for weight matrices consumed by gemm_tc.
// Element (k, n) of a [Ee][Ee] k-row-major matrix maps to:
//   kt = k/32, kin = k%32 -> kk4 = kin/8, c4 = (kin%8)/4, t = kin%4
//   nb = n/64, nin = n%64 -> wn2 = nin/32, ni = (nin%32)/8, g = nin%8
//   lane = g*4 + t; f4 = ni/2; comp = (ni%2)*2 + c4
//   addr = (kt*5 + nb)*2048 + ((wn2*4 + kk4)*2 + f4)*128 + lane*4 + comp
__device__ __forceinline__ size_t perm_addr(int k, int n) {
    int kt = k >> 5, kin = k & 31;
    int kk4 = kin >> 3, c4 = (kin >> 2) & 1, t = kin & 3;
    int nb = n >> 6, nin = n & 63;
    int wn2 = nin >> 5, ni = (nin >> 3) & 3, g = nin & 7;
    int lane = g*4 + t;
    int f4i = ni >> 1, comp = ((ni & 1) << 1) + c4;
    return (size_t)(kt*5 + nb)*2048 + (size_t)(((wn2*4 + kk4)*2 + f4i)*128 + lane*4 + comp);
}

// ---------------- precompute kernels ----------------

__global__ void transpose320(const float* __restrict__ in, float* __restrict__ out) {
    __shared__ float tile[32][33];
    int bx = blockIdx.x * 32, by = blockIdx.y * 32;
    int x = bx + threadIdx.x;
    #pragma unroll
    for (int i = 0; i < 32; i += 8) {
        int y = by + threadIdx.y + i;
        tile[threadIdx.y + i][threadIdx.x] = in[(size_t)y*Ee + x];
    }
    __syncthreads();
    x = by + threadIdx.x;
    #pragma unroll
    for (int i = 0; i < 32; i += 8) {
        int y = bx + threadIdx.y + i;
        out[(size_t)y*Ee + x] = tile[threadIdx.x][threadIdx.y + i];
    }
}

#define NCOMB 11
struct CombineBatch {
    const float* A[NCOMB];
    const float* B[NCOMB];
    float*       C[NCOMB];
    int          perm[NCOMB];   // 1 = write MMA-fragment layout, 0 = natural
};
__global__ void __launch_bounds__(256) combine_batch(CombineBatch p) {
    const float* __restrict__ A = p.A[blockIdx.z];
    const float* __restrict__ B = p.B[blockIdx.z];
    float* __restrict__ C = p.C[blockIdx.z];
    const int doperm = p.perm[blockIdx.z];
    constexpr int BK = 16;
    __shared__ float As[BK][64];
    __shared__ float Bs[BK][64];
    const int tid = threadIdx.x;
    const int bm = blockIdx.y * 64;
    const int bn = blockIdx.x * 64;
    const int tcol = tid & 15, trow = tid >> 4;
    const int aRow = tid >> 2, aCol = (tid & 3) << 2;

    float acc[4][4];
    #pragma unroll
    for (int i = 0; i < 4; i++)
        #pragma unroll
        for (int j = 0; j < 4; j++) acc[i][j] = 0.f;

    for (int k0 = 0; k0 < Ee; k0 += BK) {
        float4 a4 = *(const float4*)(A + (size_t)(bm + aRow)*Ee + k0 + aCol);
        float4 b4 = *(const float4*)(B + (size_t)(bn + aRow)*Ee + k0 + aCol);
        As[aCol+0][aRow] = a4.x; As[aCol+1][aRow] = a4.y;
        As[aCol+2][aRow] = a4.z; As[aCol+3][aRow] = a4.w;
        Bs[aCol+0][aRow] = b4.x; Bs[aCol+1][aRow] = b4.y;
        Bs[aCol+2][aRow] = b4.z; Bs[aCol+3][aRow] = b4.w;
        __syncthreads();
        #pragma unroll
        for (int kk = 0; kk < BK; kk++) {
            float ar[4], br[4];
            #pragma unroll
            for (int i = 0; i < 4; i++) ar[i] = As[kk][trow*4 + i];
            #pragma unroll
            for (int j = 0; j < 4; j++) br[j] = Bs[kk][tcol*4 + j];
            #pragma unroll
            for (int i = 0; i < 4; i++)
                #pragma unroll
                for (int j = 0; j < 4; j++)
                    acc[i][j] += ar[i] * br[j];
        }
        __syncthreads();
    }
    if (doperm) {
        #pragma unroll
        for (int i = 0; i < 4; i++)
            #pragma unroll
            for (int j = 0; j < 4; j++)
                C[perm_addr(bm + trow*4 + i, bn + tcol*4 + j)] = acc[i][j];
    } else {
        #pragma unroll
        for (int i = 0; i < 4; i++)
            #pragma unroll
            for (int j = 0; j < 4; j++)
                C[(size_t)(bm + trow*4 + i)*Ee + bn + tcol*4 + j] = acc[i][j];
    }
}

#define NBIAS 5
struct BiasBatch {
    const float* bo[NBIAS];
    const float* Bq[NBIAS];
    const float* b2[NBIAS];
    float*       out[NBIAS];
};
__global__ void __launch_bounds__(256) bias_batch(BiasBatch p) {
    int task = blockIdx.y;
    const float* __restrict__ bo = p.bo[task];
    const float* __restrict__ Bq = p.Bq[task];
    int j = (blockIdx.x * 256 + threadIdx.x) >> 5;
    int lane = threadIdx.x & 31;
    if (j >= Ee) return;
    const float* br = Bq + (size_t)j*Ee;
    float s = 0.f;
    #pragma unroll
    for (int e = lane, i = 0; i < Ee/32; e += 32, i++) s += bo[e] * br[e];
    #pragma unroll
    for (int off = 16; off > 0; off >>= 1) s += __shfl_down_sync(0xffffffffu, s, off);
    if (lane == 0) p.out[task][j] = s + p.b2[task][j];
}

__global__ void combine_fmat_w(const float* __restrict__ fowT, const float* __restrict__ W,
                               float* __restrict__ out) {
    int o = (blockIdx.x * 256 + threadIdx.x) >> 5;
    int lane = threadIdx.x & 31;
    if (o >= Ee*OUTD) return;
    int e = o / OUTD, j = o % OUTD;
    const float* fr = fowT + (size_t)e*Ee;
    float s = 0.f;
    #pragma unroll
    for (int t = lane, i = 0; i < Ee/32; t += 32, i++) s += fr[t] * W[(size_t)t*OUTD + j];
    #pragma unroll
    for (int off = 16; off > 0; off >>= 1) s += __shfl_down_sync(0xffffffffu, s, off);
    if (lane == 0) out[o] = s;
}

__global__ void combine_fbias_w(const float* __restrict__ fob, const float* __restrict__ W,
                                float* __restrict__ out) {
    int warp = threadIdx.x >> 5, lane = threadIdx.x & 31;
    for (int j = warp; j < OUTD; j += 8) {
        float s = 0.f;
        #pragma unroll
        for (int t = lane, i = 0; i < Ee/32; t += 32, i++) s += fob[t] * W[(size_t)t*OUTD + j];
        #pragma unroll
        for (int off = 16; off > 0; off >>= 1) s += __shfl_down_sync(0xffffffffu, s, off);
        if (lane == 0) out[j] = s;
    }
}

__global__ void build_rows(const int* __restrict__ in_idx, const int* __restrict__ out_idx,
                           int* __restrict__ rin, int* __restrict__ rout, int* __restrict__ rq0) {
    int n = blockIdx.x * blockDim.x + threadIdx.x;
    if (n >= Nn) return;
    rin[n*Ln] = n;
    rout[n*Ln] = n;
    rq0[n] = n*Ln;
    #pragma unroll
    for (int d = 0; d < Dn; d++) {
        rin[n*Ln + 1 + d]  = in_idx[n*Dn + d];
        rout[n*Ln + 1 + d] = out_idx[n*Dn + d];
    }
}

// ---------------- dual tensor-core multi-B GEMM, fragment-order B (grid.z=2) ----------------
// tf32 HMMA (fp32 bits fed directly; HW truncates), fp32 accumulate.
// BM=128, BN=64, BK=32, 2-stage cp.async. B matrices pre-permuted to fragment order.
struct DualArgs {
    const float* A[2];
    const int*   rows[2];
    const float* B[2][3];
    const float* bias[2][3];
    float*       C[2][3];
    int out_grp, out_str;
    int out_off[2];
};

template<int NMAT>
__global__ void __launch_bounds__(256) gemm_tc_dual(DualArgs p)
{
    constexpr int BM = 128, BN = 64, BK = 32;
    constexpr int ASTR = 36;
    constexpr int BBLK = BK * BN;   // 2048 floats per (kt, nb) fragment block
    constexpr int NT = Ee / BK;     // 10
    extern __shared__ float smp[];
    float* AsBase = smp;                      // [2][BM*ASTR]
    float* BsBase = smp + 2*BM*ASTR;          // [2][NMAT][BBLK]

    const int z = blockIdx.z;
    const float* __restrict__ A = p.A[z];
    const int* __restrict__ rows = p.rows[z];
    const int out_grp = p.out_grp, out_str = p.out_str, out_off = p.out_off[z];

    const int tid = threadIdx.x;
    const int nb = blockIdx.x;            // n-block index (64 cols each)
    const int bm = blockIdx.y * BM;
    const int bn = nb * BN;
    const int warpId = tid >> 5, lane = tid & 31;
    const int wm = (warpId & 3) * 32;
    const int wn2 = warpId >> 2;          // 0/1 -> wn = wn2*32
    const int wn = wn2 * 32;
    const int g = lane >> 2, t = lane & 3;

    const float* Bp[NMAT]; const float* biasp[NMAT]; float* Cp[NMAT];
    #pragma unroll
    for (int q = 0; q < NMAT; q++) { Bp[q] = p.B[z][q]; biasp[q] = p.bias[z][q]; Cp[q] = p.C[z][q]; }

    float acc[NMAT][2][4][4];
    #pragma unroll
    for (int q = 0; q < NMAT; q++)
        #pragma unroll
        for (int mi = 0; mi < 2; mi++)
            #pragma unroll
            for (int ni = 0; ni < 4; ni++)
                #pragma unroll
                for (int v = 0; v < 4; v++) acc[q][mi][ni][v] = 0.f;

    const int aRow = tid >> 3;
    const int aCol = (tid & 7) * 4;
    size_t gA[4];
    #pragma unroll
    for (int i = 0; i < 4; i++) {
        int m = bm + aRow + i*32;
        gA[i] = (size_t)(rows ? rows[m] : m) * Ee;
    }

    auto issue = [&](int kt, int st) {
        float* As = AsBase + st*BM*ASTR;
        #pragma unroll
        for (int i = 0; i < 4; i++)
            cp_async16(&As[(aRow + i*32)*ASTR + aCol], A + gA[i] + kt*BK + aCol);
        #pragma unroll
        for (int q = 0; q < NMAT; q++) {
            float* Bs = BsBase + (st*NMAT + q)*BBLK;
            const float* src = Bp[q] + (size_t)(kt*5 + nb)*BBLK + tid*8;
            cp_async16(&Bs[tid*8],     src);
            cp_async16(&Bs[tid*8 + 4], src + 4);
        }
    };

    auto compute = [&](int st) {
        const float* As = AsBase + st*BM*ASTR;
        #pragma unroll
        for (int kk = 0; kk < BK; kk += 8) {
            const int kk4 = kk >> 3;
            uint32_t afr[2][4];
            #pragma unroll
            for (int mi = 0; mi < 2; mi++) {
                int r0 = wm + mi*16 + g;
                afr[mi][0] = __float_as_uint(As[(r0    )*ASTR + kk + t    ]);
                afr[mi][1] = __float_as_uint(As[(r0 + 8)*ASTR + kk + t    ]);
                afr[mi][2] = __float_as_uint(As[(r0    )*ASTR + kk + t + 4]);
                afr[mi][3] = __float_as_uint(As[(r0 + 8)*ASTR + kk + t + 4]);
            }
            #pragma unroll
            for (int q = 0; q < NMAT; q++) {
                const float4* Bf = (const float4*)(BsBase + (st*NMAT + q)*BBLK);
                const int base8 = (wn2*4 + kk4)*2;
                float4 fa = Bf[(base8    )*32 + lane];   // {ni0.b0, ni0.b1, ni1.b0, ni1.b1}
                float4 fb = Bf[(base8 + 1)*32 + lane];   // {ni2.b0, ni2.b1, ni3.b0, ni3.b1}
                #pragma unroll
                for (int mi = 0; mi < 2; mi++) {
                    mma_tf32(acc[q][mi][0], afr[mi], __float_as_uint(fa.x), __float_as_uint(fa.y));
                    mma_tf32(acc[q][mi][1], afr[mi], __float_as_uint(fa.z), __float_as_uint(fa.w));
                    mma_tf32(acc[q][mi][2], afr[mi], __float_as_uint(fb.x), __float_as_uint(fb.y));
                    mma_tf32(acc[q][mi][3], afr[mi], __float_as_uint(fb.z), __float_as_uint(fb.w));
                }
            }
        }
    };

    // 2-stage double buffer (R7/R11 proven config)
    issue(0, 0);
    cp_commit();

    #pragma unroll 1
    for (int kt = 0; kt < NT; kt++) {
        int st = kt & 1;
        if (kt + 1 < NT) {
            issue(kt + 1, st ^ 1);
            cp_commit();
            asm volatile("cp.async.wait_group 1;" ::: "memory");
        } else {
            asm volatile("cp.async.wait_group 0;" ::: "memory");
        }
        __syncthreads();
        compute(st);
        __syncthreads();
    }

    // epilogue
    #pragma unroll
    for (int q = 0; q < NMAT; q++) {
        #pragma unroll
        for (int ni = 0; ni < 4; ni++) {
            int n = bn + wn + ni*8 + 2*t;
            float bb0 = biasp[q][n], bb1 = biasp[q][n+1];
            #pragma unroll
            for (int mi = 0; mi < 2; mi++) {
                int m0 = bm + wm + mi*16 + g;
                int m1 = m0 + 8;
                int cr0 = (m0 / out_grp) * out_str + (m0 % out_grp) + out_off;
                int cr1 = (m1 / out_grp) * out_str + (m1 % out_grp) + out_off;
                float2 v0, v1;
                v0.x = acc[q][mi][ni][0] + bb0; v0.y = acc[q][mi][ni][1] + bb1;
                v1.x = acc[q][mi][ni][2] + bb0; v1.y = acc[q][mi][ni][3] + bb1;
                *(float2*)(Cp[q] + (size_t)cr0*Ee + n) = v0;
                *(float2*)(Cp[q] + (size_t)cr1*Ee + n) = v1;
            }
        }
    }
}

// ---------------- single-B SIMT GEMM with M guard (q0: M = 10000, fp32 exact) ----------------
__global__ void __launch_bounds__(256) gemm320(
    const float* __restrict__ A, const int* __restrict__ rows, int M,
    const float* __restrict__ B, const float* __restrict__ bias,
    float* __restrict__ C)
{
    constexpr int BM = 64, BN = 64, BK = 16;
    __shared__ float As[BK][BM];
    __shared__ float Bs[BK][BN];
    const int tid = threadIdx.x;
    const int bm = blockIdx.y * BM;
    const int bn = blockIdx.x * BN;
    const int tcol = tid & 15;
    const int trow = tid >> 4;

    float acc[4][4];
    #pragma unroll
    for (int i = 0; i < 4; i++)
        #pragma unroll
        for (int j = 0; j < 4; j++) acc[i][j] = 0.f;

    const int aRow = tid >> 2;
    const int aCol = (tid & 3) << 2;
    int r = bm + aRow; if (r >= M) r = M - 1;
    const size_t ga = (size_t)(rows ? rows[r] : r) * Ee;
    const int bRow = tid >> 4;
    const int bCol = (tid & 15) << 2;

    for (int k0 = 0; k0 < Ee; k0 += BK) {
        float4 a4 = *(const float4*)(A + ga + k0 + aCol);
        float4 b4 = *(const float4*)(B + (size_t)(k0 + bRow)*Ee + bn + bCol);
        As[aCol+0][aRow] = a4.x; As[aCol+1][aRow] = a4.y;
        As[aCol+2][aRow] = a4.z; As[aCol+3][aRow] = a4.w;
        *(float4*)&Bs[bRow][bCol] = b4;
        __syncthreads();

        #pragma unroll
        for (int kk = 0; kk < BK; kk++) {
            float ar[4], br[4];
            #pragma unroll
            for (int i = 0; i < 4; i++) ar[i] = As[kk][trow*4 + i];
            #pragma unroll
            for (int j = 0; j < 4; j++) br[j] = Bs[kk][tcol*4 + j];
            #pragma unroll
            for (int i = 0; i < 4; i++)
                #pragma unroll
                for (int j = 0; j < 4; j++)
                    acc[i][j] += ar[i] * br[j];
        }
        __syncthreads();
    }

    float bb[4];
    #pragma unroll
    for (int j = 0; j < 4; j++) bb[j] = bias[bn + tcol*4 + j];
    #pragma unroll
    for (int i = 0; i < 4; i++) {
        int m = bm + trow*4 + i;
        if (m < M) {
            float4 o;
            o.x = acc[i][0] + bb[0];
            o.y = acc[i][1] + bb[1];
            o.z = acc[i][2] + bb[2];
            o.w = acc[i][3] + bb[3];
            *(float4*)(C + (size_t)m*Ee + bn + tcol*4) = o;
        }
    }
}

// ---------------- merged per-node 5-head attention: blocks [0,Nn)->in, [Nn,2Nn)->out ----------------
__global__ void __launch_bounds__(256) attn16_dual(
    const float* __restrict__ Q1, const float* __restrict__ K1,
    const float* __restrict__ V1, float* __restrict__ O1,
    const float* __restrict__ Q2, const float* __restrict__ K2,
    const float* __restrict__ V2, float* __restrict__ O2)
{
    constexpr int LP = 68;
    __shared__ float sq[Ln][LP], sk[Ln][LP], sv[Ln][LP];
    __shared__ float ss[Ln][Ln + 1];
    int n = blockIdx.x;
    const float *Q, *K, *V; float* O;
    if (n < Nn) { Q = Q1; K = K1; V = V1; O = O1; }
    else        { Q = Q2; K = K2; V = V2; O = O2; n -= Nn; }
    const int tid = threadIdx.x;
    const size_t base = (size_t)n * Ln * Ee;

    const int ll = tid >> 4;          // 0..15
    const int lc = (tid & 15) << 2;   // 0..60

    for (int h = 0; h < NH; h++) {
        const int hc = h * HD;
        float4 q4 = *(const float4*)(Q + base + (size_t)ll*Ee + hc + lc);
        float4 k4 = *(const float4*)(K + base + (size_t)ll*Ee + hc + lc);
        float4 v4 = *(const float4*)(V + base + (size_t)ll*Ee + hc + lc);
        *(float4*)&sq[ll][lc] = q4;
        *(float4*)&sk[ll][lc] = k4;
        *(float4*)&sv[ll][lc] = v4;
        __syncthreads();

        {
            const int sl = tid >> 4, sm = tid & 15;
            float s = 0.f;
            #pragma unroll
            for (int c = 0; c < HD; c += 4) {
                float4 qv = *(const float4*)&sq[sl][c];
                float4 kv = *(const float4*)&sk[sm][c];
                s += qv.x*kv.x + qv.y*kv.y + qv.z*kv.z + qv.w*kv.w;
            }
            s *= 0.125f;  // 1/sqrt(64)
            float mx = s;
            #pragma unroll
            for (int o = 8; o > 0; o >>= 1) mx = fmaxf(mx, __shfl_xor_sync(0xffffffffu, mx, o));
            float ex = expf(s - mx);
            float sum = ex;
            #pragma unroll
            for (int o = 8; o > 0; o >>= 1) sum += __shfl_xor_sync(0xffffffffu, sum, o);
            ss[sl][sm] = ex / sum;
        }
        __syncthreads();

        {
            const int ol = tid >> 4;
            const int ocg = (tid & 15) << 2;
            float4 a = make_float4(0.f, 0.f, 0.f, 0.f);
            #pragma unroll
            for (int m = 0; m < Ln; m++) {
                float w = ss[ol][m];
                float4 vv = *(const float4*)&sv[m][ocg];
                a.x += w*vv.x; a.y += w*vv.y; a.z += w*vv.z; a.w += w*vv.w;
            }
            *(float4*)(O + base + (size_t)ol*Ee + hc + ocg) = a;
        }
        __syncthreads();
    }
}

// ---------------- final 1-head attention over 32 tokens + fused output proj + ELU ----------------
__global__ void __launch_bounds__(256) final_attn(
    const float* __restrict__ q0, const float* __restrict__ Kf,
    const float* __restrict__ Vf, const float* __restrict__ Fmat,
    const float* __restrict__ fbias, float* __restrict__ out)
{
    __shared__ float sqv[Ee];
    __shared__ float sc[32];
    __shared__ float so[Ee];
    const int n = blockIdx.x;
    const int tid = threadIdx.x;
    const int warp = tid >> 5, lane = tid & 31;
    const float scale = 0.05590169943749474f;  // 1/sqrt(320)

    if (tid < Ee/4) {
        ((float4*)sqv)[tid] = ((const float4*)(q0 + (size_t)n*Ee))[tid];
    }
    __syncthreads();

    #pragma unroll
    for (int i = 0; i < 4; i++) {
        int m = warp*4 + i;
        const float4* kr = (const float4*)(Kf + ((size_t)n*32 + m) * Ee);
        float s = 0.f;
        #pragma unroll 1
        for (int f = lane; f < Ee/4; f += 32) {
            float4 kv = kr[f];
            float4 qv = ((const float4*)sqv)[f];
            s += qv.x*kv.x + qv.y*kv.y + qv.z*kv.z + qv.w*kv.w;
        }
        #pragma unroll
        for (int o = 16; o > 0; o >>= 1) s += __shfl_down_sync(0xffffffffu, s, o);
        if (lane == 0) sc[m] = s * scale;
    }
    __syncthreads();

    if (warp == 0) {
        float v = sc[lane];
        float mx = v;
        #pragma unroll
        for (int o = 16; o > 0; o >>= 1) mx = fmaxf(mx, __shfl_xor_sync(0xffffffffu, mx, o));
        float ex = expf(v - mx);
        float sm = ex;
        #pragma unroll
        for (int o = 16; o > 0; o >>= 1) sm += __shfl_xor_sync(0xffffffffu, sm, o);
        sc[lane] = ex / sm;
    }
    __syncthreads();

    for (int e = tid; e < Ee; e += 256) {
        const float* vr = Vf + (size_t)n*32*Ee + e;
        float a = 0.f;
        #pragma unroll
        for (int m = 0; m < 32; m++) a += sc[m] * vr[(size_t)m*Ee];
        so[e] = a;
    }
    __syncthreads();

    #pragma unroll
    for (int i = 0; i < 4; i++) {
        int j = warp*4 + i;
        if (j < OUTD) {
            float s = 0.f;
            for (int e = lane; e < Ee; e += 32) s += so[e] * Fmat[(size_t)e*OUTD + j];
            #pragma unroll
            for (int o = 16; o > 0; o >>= 1) s += __shfl_down_sync(0xffffffffu, s, o);
            if (lane == 0) {
                float x = s + fbias[j];
                out[(size_t)n*OUTD + j] = x > 0.f ? x : expm1f(x);
            }
        }
    }
}

// ---------------- host ----------------
#define GETSYM(p, s) do { void* _t; cudaGetSymbolAddress(&_t, s); p = decltype(p)(_t); } while (0)

extern "C" void kernel_launch(void* const* d_in, const int* in_sizes, int n_in,
                              void* d_out, int out_size)
{
    const float* X        = (const float*)d_in[0];
    const int*   in_idx   = (const int*)  d_in[1];
    const int*   out_idx  = (const int*)  d_in[2];
    const float* in_Wq    = (const float*)d_in[3];
    const float* in_Wk    = (const float*)d_in[4];
    const float* in_Wv    = (const float*)d_in[5];
    const float* in_qkv_w = (const float*)d_in[6];
    const float* in_qkv_b = (const float*)d_in[7];
    const float* in_o_w   = (const float*)d_in[8];
    const float* in_o_b   = (const float*)d_in[9];
    const float* out_Wq   = (const float*)d_in[10];
    const float* out_Wk   = (const float*)d_in[11];
    const float* out_Wv   = (const float*)d_in[12];
    const float* out_qkv_w= (const float*)d_in[13];
    const float* out_qkv_b= (const float*)d_in[14];
    const float* out_o_w  = (const float*)d_in[15];
    const float* out_o_b  = (const float*)d_in[16];
    const float* fin_qkv_w= (const float*)d_in[17];
    const float* fin_qkv_b= (const float*)d_in[18];
    const float* fin_o_w  = (const float*)d_in[19];
    const float* fin_o_b  = (const float*)d_in[20];
    const float* Wfin     = (const float*)d_in[21];
    float* out = (float*)d_out;

    float *Mq_in, *Mk_in, *Mv_in, *Mq_out, *Mk_out, *Mv_out;
    float *Qmat, *Kmat_in, *Kmat_out, *Vmat_in, *Vmat_out;
    float *T_in_o, *T_out_o, *T_fin_o;
    float *qbias, *kbias_in, *kbias_out, *vbias_in, *vbias_out;
    float *Fmat, *fbias, *Q, *K, *V, *Q2, *K2, *V2, *Oin, *Oout, *Kf, *Vf, *q0;
    int *rows_in, *rows_out, *rows_q0;
    GETSYM(Mq_in, g_Mq_in);   GETSYM(Mk_in, g_Mk_in);   GETSYM(Mv_in, g_Mv_in);
    GETSYM(Mq_out, g_Mq_out); GETSYM(Mk_out, g_Mk_out); GETSYM(Mv_out, g_Mv_out);
    GETSYM(Qmat, g_Qmat);     GETSYM(Kmat_in, g_Kmat_in); GETSYM(Kmat_out, g_Kmat_out);
    GETSYM(Vmat_in, g_Vmat_in); GETSYM(Vmat_out, g_Vmat_out);
    GETSYM(T_in_o, g_T_in_o); GETSYM(T_out_o, g_T_out_o); GETSYM(T_fin_o, g_T_fin_o);
    GETSYM(qbias, g_qbias);   GETSYM(kbias_in, g_kbias_in); GETSYM(kbias_out, g_kbias_out);
    GETSYM(vbias_in, g_vbias_in); GETSYM(vbias_out, g_vbias_out);
    GETSYM(Fmat, g_Fmat);     GETSYM(fbias, g_fbias);
    GETSYM(Q, g_Q); GETSYM(K, g_K); GETSYM(V, g_V);
    GETSYM(Q2, g_Q2); GETSYM(K2, g_K2); GETSYM(V2, g_V2);
    GETSYM(Oin, g_Oin); GETSYM(Oout, g_Oout);
    GETSYM(Kf, g_Kf); GETSYM(Vf, g_Vf); GETSYM(q0, g_q0);
    GETSYM(rows_in, g_rows_in); GETSYM(rows_out, g_rows_out); GETSYM(rows_q0, g_rows_q0);

    const int CB = 256;

    // dynamic smem opt-in for the 2-stage fragment-order GEMMs
    const int SMEM3 = (2*128*36 + 2*3*2048) * 4;   // 86016
    const int SMEM2 = (2*128*36 + 2*2*2048) * 4;   // 69632
    cudaFuncSetAttribute(gemm_tc_dual<3>, cudaFuncAttributeMaxDynamicSharedMemorySize, SMEM3);
    cudaFuncSetAttribute(gemm_tc_dual<2>, cudaFuncAttributeMaxDynamicSharedMemorySize, SMEM2);

    // 1) row gather tables + transposes of the three output-proj matrices
    build_rows<<<(Nn + CB - 1)/CB, CB>>>(in_idx, out_idx, rows_in, rows_out, rows_q0);
    dim3 tG(10, 10), tB(32, 8);
    transpose320<<<tG, tB>>>(in_o_w,  T_in_o);
    transpose320<<<tG, tB>>>(out_o_w, T_out_o);
    transpose320<<<tG, tB>>>(fin_o_w, T_fin_o);

    // 2+3) all 11 combined matrices in ONE batched launch: C = A @ B^T
    // Tasks consumed by gemm_tc get the MMA-fragment layout; Qmat (task 6) stays natural.
    CombineBatch cb;
    cb.A[0] = in_Wq;   cb.B[0] = in_qkv_w;            cb.C[0] = Mq_in;    cb.perm[0] = 1;
    cb.A[1] = in_Wk;   cb.B[1] = in_qkv_w + Ee*Ee;    cb.C[1] = Mk_in;    cb.perm[1] = 1;
    cb.A[2] = in_Wv;   cb.B[2] = in_qkv_w + 2*Ee*Ee;  cb.C[2] = Mv_in;    cb.perm[2] = 1;
    cb.A[3] = out_Wq;  cb.B[3] = out_qkv_w;           cb.C[3] = Mq_out;   cb.perm[3] = 1;
    cb.A[4] = out_Wk;  cb.B[4] = out_qkv_w + Ee*Ee;   cb.C[4] = Mk_out;   cb.perm[4] = 1;
    cb.A[5] = out_Wv;  cb.B[5] = out_qkv_w + 2*Ee*Ee; cb.C[5] = Mv_out;   cb.perm[5] = 1;
    cb.A[6] = T_in_o;  cb.B[6] = fin_qkv_w;           cb.C[6] = Qmat;     cb.perm[6] = 0;
    cb.A[7] = T_in_o;  cb.B[7] = fin_qkv_w + Ee*Ee;   cb.C[7] = Kmat_in;  cb.perm[7] = 1;
    cb.A[8] = T_out_o; cb.B[8] = fin_qkv_w + Ee*Ee;   cb.C[8] = Kmat_out; cb.perm[8] = 1;
    cb.A[9] = T_in_o;  cb.B[9] = fin_qkv_w + 2*Ee*Ee; cb.C[9] = Vmat_in;  cb.perm[9] = 1;
    cb.A[10]= T_out_o; cb.B[10]= fin_qkv_w + 2*Ee*Ee; cb.C[10]= Vmat_out; cb.perm[10]= 1;
    combine_batch<<<dim3(5, 5, NCOMB), CB>>>(cb);

    BiasBatch bb;
    bb.bo[0] = in_o_b;  bb.Bq[0] = fin_qkv_w;           bb.b2[0] = fin_qkv_b;          bb.out[0] = qbias;
    bb.bo[1] = in_o_b;  bb.Bq[1] = fin_qkv_w + Ee*Ee;   bb.b2[1] = fin_qkv_b + Ee;     bb.out[1] = kbias_in;
    bb.bo[2] = out_o_b; bb.Bq[2] = fin_qkv_w + Ee*Ee;   bb.b2[2] = fin_qkv_b + Ee;     bb.out[2] = kbias_out;
    bb.bo[3] = in_o_b;  bb.Bq[3] = fin_qkv_w + 2*Ee*Ee; bb.b2[3] = fin_qkv_b + 2*Ee;   bb.out[3] = vbias_in;
    bb.bo[4] = out_o_b; bb.Bq[4] = fin_qkv_w + 2*Ee*Ee; bb.b2[4] = fin_qkv_b + 2*Ee;   bb.out[4] = vbias_out;
    bias_batch<<<dim3(40, NBIAS), CB>>>(bb);

    // 4) fold final output-proj into readout: Fmat = wof.T @ W
    combine_fmat_w<<<(Ee*OUTD + 7)/8, CB>>>(T_fin_o, Wfin, Fmat);
    combine_fbias_w<<<1, CB>>>(fin_o_b, Wfin, fbias);

    const int Mfull = Nn * Ln;           // 160000 = 1250 * 128

    // 5+6) BOTH layers' Q/K/V in one dual launch, then both attentions in one launch
    DualArgs d3;
    d3.A[0] = X;  d3.A[1] = X;
    d3.rows[0] = rows_in;  d3.rows[1] = rows_out;
    d3.B[0][0] = Mq_in;  d3.B[0][1] = Mk_in;  d3.B[0][2] = Mv_in;
    d3.B[1][0] = Mq_out; d3.B[1][1] = Mk_out; d3.B[1][2] = Mv_out;
    d3.bias[0][0] = in_qkv_b;  d3.bias[0][1] = in_qkv_b + Ee;  d3.bias[0][2] = in_qkv_b + 2*Ee;
    d3.bias[1][0] = out_qkv_b; d3.bias[1][1] = out_qkv_b + Ee; d3.bias[1][2] = out_qkv_b + 2*Ee;
    d3.C[0][0] = Q;  d3.C[0][1] = K;  d3.C[0][2] = V;
    d3.C[1][0] = Q2; d3.C[1][1] = K2; d3.C[1][2] = V2;
    d3.out_grp = 16; d3.out_str = 16; d3.out_off[0] = 0; d3.out_off[1] = 0;
    gemm_tc_dual<3><<<dim3(Ee/64, Mfull/128, 2), 256, SMEM3>>>(d3);

    attn16_dual<<<2*Nn, 256>>>(Q, K, V, Oin, Q2, K2, V2, Oout);

    // 7) final-layer K/V: both sources in one dual launch (interleaved halves)
    DualArgs d2;
    d2.A[0] = Oin;  d2.A[1] = Oout;
    d2.rows[0] = nullptr; d2.rows[1] = nullptr;
    d2.B[0][0] = Kmat_in;  d2.B[0][1] = Vmat_in;  d2.B[0][2] = nullptr;
    d2.B[1][0] = Kmat_out; d2.B[1][1] = Vmat_out; d2.B[1][2] = nullptr;
    d2.bias[0][0] = kbias_in;  d2.bias[0][1] = vbias_in;  d2.bias[0][2] = nullptr;
    d2.bias[1][0] = kbias_out; d2.bias[1][1] = vbias_out; d2.bias[1][2] = nullptr;
    d2.C[0][0] = Kf; d2.C[0][1] = Vf; d2.C[0][2] = nullptr;
    d2.C[1][0] = Kf; d2.C[1][1] = Vf; d2.C[1][2] = nullptr;
    d2.out_grp = 16; d2.out_str = 32; d2.out_off[0] = 0; d2.out_off[1] = 16;
    gemm_tc_dual<2><<<dim3(Ee/64, Mfull/128, 2), 256, SMEM2>>>(d2);

    gemm320<<<dim3(Ee/64, (Nn + 63)/64), 256>>>(Oin, rows_q0, Nn, Qmat, qbias, q0);

    // 8) final attention + fused readout + ELU
    final_attn<<<Nn, 256>>>(q0, Kf, Vf, Fmat, fbias, out);
}

// round 16
// speedup vs baseline: 1.2903x; 1.1691x over previous
#include <cuda_runtime.h>
#include <math.h>
#include <stdint.h>

#define Nn 10000
#define Dn 15
#define Ln 16
#define Ee 320
#define OUTD 30
#define NH 5
#define HD 64

// ---------------- scratch (static device globals; no allocation) ----------------
__device__ float g_Mq_in[Ee*Ee], g_Mk_in[Ee*Ee], g_Mv_in[Ee*Ee];
__device__ float g_Mq_out[Ee*Ee], g_Mk_out[Ee*Ee], g_Mv_out[Ee*Ee];
__device__ float g_Qmat[Ee*Ee], g_Kmat_in[Ee*Ee], g_Kmat_out[Ee*Ee];
__device__ float g_Vmat_in[Ee*Ee], g_Vmat_out[Ee*Ee];
__device__ float g_T_in_o[Ee*Ee], g_T_out_o[Ee*Ee], g_T_fin_o[Ee*Ee];
__device__ float g_qbias[Ee], g_kbias_in[Ee], g_kbias_out[Ee], g_vbias_in[Ee], g_vbias_out[Ee];
__device__ float g_Fmat[Ee*OUTD], g_fbias[OUTD];
__device__ int   g_rows_in[Nn*Ln], g_rows_out[Nn*Ln], g_rows_q0[Nn];
__device__ float g_Oin[(size_t)Nn*Ln*Ee], g_Oout[(size_t)Nn*Ln*Ee];
__device__ float g_Kf[(size_t)Nn*2*Ln*Ee], g_Vf[(size_t)Nn*2*Ln*Ee];
__device__ float g_q0[(size_t)Nn*Ee];

// ---------------- helpers ----------------
__device__ __forceinline__ void mma_tf32(float* d, const uint32_t* a, uint32_t b0, uint32_t b1) {
    asm volatile(
        "mma.sync.aligned.m16n8k8.row.col.f32.tf32.tf32.f32 "
        "{%0,%1,%2,%3}, {%4,%5,%6,%7}, {%8,%9}, {%0,%1,%2,%3};"
        : "+f"(d[0]), "+f"(d[1]), "+f"(d[2]), "+f"(d[3])
        : "r"(a[0]), "r"(a[1]), "r"(a[2]), "r"(a[3]), "r"(b0), "r"(b1));
}

__device__ __forceinline__ void cp_async16(void* smem_dst, const void* gmem_src) {
    uint32_t d = (uint32_t)__cvta_generic_to_shared(smem_dst);
    asm volatile("cp.async.cg.shared.global [%0], [%1], 16;" :: "r"(d), "l"(gmem_src));
}
__device__ __forceinline__ void cp_commit() {
    asm volatile("cp.async.commit_group;" ::: "memory");
}

// Permuted (MMA-fragment-order) address for weight matrices consumed by the tc GEMMs.
__device__ __forceinline__ size_t perm_addr(int k, int n) {
    int kt = k >> 5, kin = k & 31;
    int kk4 = kin >> 3, c4 = (kin >> 2) & 1, t = kin & 3;
    int nb = n >> 6, nin = n & 63;
    int wn2 = nin >> 5, ni = (nin >> 3) & 3, g = nin & 7;
    int lane = g*4 + t;
    int f4i = ni >> 1, comp = ((ni & 1) << 1) + c4;
    return (size_t)(kt*5 + nb)*2048 + (size_t)(((wn2*4 + kk4)*2 + f4i)*128 + lane*4 + comp);
}

// ---------------- precompute kernels ----------------

__global__ void transpose320(const float* __restrict__ in, float* __restrict__ out) {
    __shared__ float tile[32][33];
    int bx = blockIdx.x * 32, by = blockIdx.y * 32;
    int x = bx + threadIdx.x;
    #pragma unroll
    for (int i = 0; i < 32; i += 8) {
        int y = by + threadIdx.y + i;
        tile[threadIdx.y + i][threadIdx.x] = in[(size_t)y*Ee + x];
    }
    __syncthreads();
    x = by + threadIdx.x;
    #pragma unroll
    for (int i = 0; i < 32; i += 8) {
        int y = bx + threadIdx.y + i;
        out[(size_t)y*Ee + x] = tile[threadIdx.x][threadIdx.y + i];
    }
}

#define NCOMB 11
struct CombineBatch {
    const float* A[NCOMB];
    const float* B[NCOMB];
    float*       C[NCOMB];
    int          perm[NCOMB];
};
__global__ void __launch_bounds__(256) combine_batch(CombineBatch p) {
    const float* __restrict__ A = p.A[blockIdx.z];
    const float* __restrict__ B = p.B[blockIdx.z];
    float* __restrict__ C = p.C[blockIdx.z];
    const int doperm = p.perm[blockIdx.z];
    constexpr int BK = 16;
    __shared__ float As[BK][64];
    __shared__ float Bs[BK][64];
    const int tid = threadIdx.x;
    const int bm = blockIdx.y * 64;
    const int bn = blockIdx.x * 64;
    const int tcol = tid & 15, trow = tid >> 4;
    const int aRow = tid >> 2, aCol = (tid & 3) << 2;

    float acc[4][4];
    #pragma unroll
    for (int i = 0; i < 4; i++)
        #pragma unroll
        for (int j = 0; j < 4; j++) acc[i][j] = 0.f;

    for (int k0 = 0; k0 < Ee; k0 += BK) {
        float4 a4 = *(const float4*)(A + (size_t)(bm + aRow)*Ee + k0 + aCol);
        float4 b4 = *(const float4*)(B + (size_t)(bn + aRow)*Ee + k0 + aCol);
        As[aCol+0][aRow] = a4.x; As[aCol+1][aRow] = a4.y;
        As[aCol+2][aRow] = a4.z; As[aCol+3][aRow] = a4.w;
        Bs[aCol+0][aRow] = b4.x; Bs[aCol+1][aRow] = b4.y;
        Bs[aCol+2][aRow] = b4.z; Bs[aCol+3][aRow] = b4.w;
        __syncthreads();
        #pragma unroll
        for (int kk = 0; kk < BK; kk++) {
            float ar[4], br[4];
            #pragma unroll
            for (int i = 0; i < 4; i++) ar[i] = As[kk][trow*4 + i];
            #pragma unroll
            for (int j = 0; j < 4; j++) br[j] = Bs[kk][tcol*4 + j];
            #pragma unroll
            for (int i = 0; i < 4; i++)
                #pragma unroll
                for (int j = 0; j < 4; j++)
                    acc[i][j] += ar[i] * br[j];
        }
        __syncthreads();
    }
    if (doperm) {
        #pragma unroll
        for (int i = 0; i < 4; i++)
            #pragma unroll
            for (int j = 0; j < 4; j++)
                C[perm_addr(bm + trow*4 + i, bn + tcol*4 + j)] = acc[i][j];
    } else {
        #pragma unroll
        for (int i = 0; i < 4; i++)
            #pragma unroll
            for (int j = 0; j < 4; j++)
                C[(size_t)(bm + trow*4 + i)*Ee + bn + tcol*4 + j] = acc[i][j];
    }
}

#define NBIAS 5
struct BiasBatch {
    const float* bo[NBIAS];
    const float* Bq[NBIAS];
    const float* b2[NBIAS];
    float*       out[NBIAS];
};
__global__ void __launch_bounds__(256) bias_batch(BiasBatch p) {
    int task = blockIdx.y;
    const float* __restrict__ bo = p.bo[task];
    const float* __restrict__ Bq = p.Bq[task];
    int j = (blockIdx.x * 256 + threadIdx.x) >> 5;
    int lane = threadIdx.x & 31;
    if (j >= Ee) return;
    const float* br = Bq + (size_t)j*Ee;
    float s = 0.f;
    #pragma unroll
    for (int e = lane, i = 0; i < Ee/32; e += 32, i++) s += bo[e] * br[e];
    #pragma unroll
    for (int off = 16; off > 0; off >>= 1) s += __shfl_down_sync(0xffffffffu, s, off);
    if (lane == 0) p.out[task][j] = s + p.b2[task][j];
}

__global__ void combine_fmat_w(const float* __restrict__ fowT, const float* __restrict__ W,
                               float* __restrict__ out) {
    int o = (blockIdx.x * 256 + threadIdx.x) >> 5;
    int lane = threadIdx.x & 31;
    if (o >= Ee*OUTD) return;
    int e = o / OUTD, j = o % OUTD;
    const float* fr = fowT + (size_t)e*Ee;
    float s = 0.f;
    #pragma unroll
    for (int t = lane, i = 0; i < Ee/32; t += 32, i++) s += fr[t] * W[(size_t)t*OUTD + j];
    #pragma unroll
    for (int off = 16; off > 0; off >>= 1) s += __shfl_down_sync(0xffffffffu, s, off);
    if (lane == 0) out[o] = s;
}

__global__ void combine_fbias_w(const float* __restrict__ fob, const float* __restrict__ W,
                                float* __restrict__ out) {
    int warp = threadIdx.x >> 5, lane = threadIdx.x & 31;
    for (int j = warp; j < OUTD; j += 8) {
        float s = 0.f;
        #pragma unroll
        for (int t = lane, i = 0; i < Ee/32; t += 32, i++) s += fob[t] * W[(size_t)t*OUTD + j];
        #pragma unroll
        for (int off = 16; off > 0; off >>= 1) s += __shfl_down_sync(0xffffffffu, s, off);
        if (lane == 0) out[j] = s;
    }
}

__global__ void build_rows(const int* __restrict__ in_idx, const int* __restrict__ out_idx,
                           int* __restrict__ rin, int* __restrict__ rout, int* __restrict__ rq0) {
    int n = blockIdx.x * blockDim.x + threadIdx.x;
    if (n >= Nn) return;
    rin[n*Ln] = n;
    rout[n*Ln] = n;
    rq0[n] = n*Ln;
    #pragma unroll
    for (int d = 0; d < Dn; d++) {
        rin[n*Ln + 1 + d]  = in_idx[n*Dn + d];
        rout[n*Ln + 1 + d] = out_idx[n*Dn + d];
    }
}

// ---------------- args structs ----------------
struct DualArgs {
    const float* A[2];
    const int*   rows[2];
    const float* B[2][3];
    const float* bias[2][3];
    float*       C[2][3];
    int out_grp, out_str;
    int out_off[2];
};

// ================= FUSED QKV GEMM + 5-head attention (grid.z selects layer) =================
// One block: 128 rows (8 nodes x 16 tokens) x 64 cols (one full head).
// Computes Q,K,V tiles on tensor cores, runs attention in smem, writes O directly.
__global__ void __launch_bounds__(256) gemm_attn_dual(DualArgs p)
{
    constexpr int BM = 128, BK = 32;
    constexpr int ASTR = 36;
    constexpr int BBLK = BK * 64;   // 2048 floats per (kt, nb) fragment block
    constexpr int NT = Ee / BK;     // 10
    constexpr int TSTR = 68;        // attention tile stride: 68*4=272B, 16B-aligned every row
    extern __shared__ float smp[];
    float* AsBase = smp;                      // [2][BM*ASTR]
    float* BsBase = smp + 2*BM*ASTR;          // [2][3][BBLK]

    const int z = blockIdx.z;
    const float* __restrict__ A = p.A[z];
    const int* __restrict__ rows = p.rows[z];

    const int tid = threadIdx.x;
    const int nb = blockIdx.x;            // head index (64 cols)
    const int bm = blockIdx.y * BM;
    const int bn = nb * 64;
    const int warpId = tid >> 5, lane = tid & 31;
    const int wm = (warpId & 3) * 32;
    const int wn2 = warpId >> 2;
    const int wn = wn2 * 32;
    const int g = lane >> 2, t = lane & 3;

    const float* Bp[3]; const float* biasp[3];
    #pragma unroll
    for (int q = 0; q < 3; q++) { Bp[q] = p.B[z][q]; biasp[q] = p.bias[z][q]; }
    float* __restrict__ O = p.C[z][0];

    float acc[3][2][4][4];
    #pragma unroll
    for (int q = 0; q < 3; q++)
        #pragma unroll
        for (int mi = 0; mi < 2; mi++)
            #pragma unroll
            for (int ni = 0; ni < 4; ni++)
                #pragma unroll
                for (int v = 0; v < 4; v++) acc[q][mi][ni][v] = 0.f;

    const int aRow = tid >> 3;
    const int aCol = (tid & 7) * 4;
    size_t gA[4];
    #pragma unroll
    for (int i = 0; i < 4; i++) {
        int m = bm + aRow + i*32;
        gA[i] = (size_t)rows[m] * Ee;
    }

    auto issue = [&](int kt, int st) {
        float* As = AsBase + st*BM*ASTR;
        #pragma unroll
        for (int i = 0; i < 4; i++)
            cp_async16(&As[(aRow + i*32)*ASTR + aCol], A + gA[i] + kt*BK + aCol);
        #pragma unroll
        for (int q = 0; q < 3; q++) {
            float* Bs = BsBase + (st*3 + q)*BBLK;
            const float* src = Bp[q] + (size_t)(kt*5 + nb)*BBLK + tid*8;
            cp_async16(&Bs[tid*8],     src);
            cp_async16(&Bs[tid*8 + 4], src + 4);
        }
    };

    auto compute = [&](int st) {
        const float* As = AsBase + st*BM*ASTR;
        #pragma unroll
        for (int kk = 0; kk < BK; kk += 8) {
            const int kk4 = kk >> 3;
            uint32_t afr[2][4];
            #pragma unroll
            for (int mi = 0; mi < 2; mi++) {
                int r0 = wm + mi*16 + g;
                afr[mi][0] = __float_as_uint(As[(r0    )*ASTR + kk + t    ]);
                afr[mi][1] = __float_as_uint(As[(r0 + 8)*ASTR + kk + t    ]);
                afr[mi][2] = __float_as_uint(As[(r0    )*ASTR + kk + t + 4]);
                afr[mi][3] = __float_as_uint(As[(r0 + 8)*ASTR + kk + t + 4]);
            }
            #pragma unroll
            for (int q = 0; q < 3; q++) {
                const float4* Bf = (const float4*)(BsBase + (st*3 + q)*BBLK);
                const int base8 = (wn2*4 + kk4)*2;
                float4 fa = Bf[(base8    )*32 + lane];
                float4 fb = Bf[(base8 + 1)*32 + lane];
                #pragma unroll
                for (int mi = 0; mi < 2; mi++) {
                    mma_tf32(acc[q][mi][0], afr[mi], __float_as_uint(fa.x), __float_as_uint(fa.y));
                    mma_tf32(acc[q][mi][1], afr[mi], __float_as_uint(fa.z), __float_as_uint(fa.w));
                    mma_tf32(acc[q][mi][2], afr[mi], __float_as_uint(fb.x), __float_as_uint(fb.y));
                    mma_tf32(acc[q][mi][3], afr[mi], __float_as_uint(fb.z), __float_as_uint(fb.w));
                }
            }
        }
    };

    issue(0, 0);
    cp_commit();

    #pragma unroll 1
    for (int kt = 0; kt < NT; kt++) {
        int st = kt & 1;
        if (kt + 1 < NT) {
            issue(kt + 1, st ^ 1);
            cp_commit();
            asm volatile("cp.async.wait_group 1;" ::: "memory");
        } else {
            asm volatile("cp.async.wait_group 0;" ::: "memory");
        }
        __syncthreads();
        compute(st);
        __syncthreads();
    }

    // ---- fused attention epilogue (pipeline smem is dead; reuse it) ----
    float* sQ = smp;                      // [128][68]
    float* sK = smp + 128*TSTR;
    float* sV = smp + 2*128*TSTR;
    float* ss = smp + 3*128*TSTR;         // [128][17]

    // stage Q,K,V (+bias) into smem tiles
    #pragma unroll
    for (int q = 0; q < 3; q++) {
        float* sX = smp + q*128*TSTR;
        #pragma unroll
        for (int ni = 0; ni < 4; ni++) {
            int c = wn + ni*8 + 2*t;
            float bb0 = biasp[q][bn + c], bb1 = biasp[q][bn + c + 1];
            #pragma unroll
            for (int mi = 0; mi < 2; mi++) {
                int r0 = wm + mi*16 + g;
                sX[r0*TSTR + c]         = acc[q][mi][ni][0] + bb0;
                sX[r0*TSTR + c + 1]     = acc[q][mi][ni][1] + bb1;
                sX[(r0+8)*TSTR + c]     = acc[q][mi][ni][2] + bb0;
                sX[(r0+8)*TSTR + c + 1] = acc[q][mi][ni][3] + bb1;
            }
        }
    }
    __syncthreads();

    // scores + softmax: half-warp hw handles 8 rows of one node; lane sm = key index
    {
        const int hw = tid >> 4;          // 0..15
        const int nd = hw >> 1;           // node 0..7
        const int sm = tid & 15;
        const int slbase = (hw & 1) * 8;
        const float* kRow = sK + (nd*16 + sm)*TSTR;
        #pragma unroll
        for (int i = 0; i < 8; i++) {
            int R = nd*16 + slbase + i;
            const float* qRow = sQ + R*TSTR;
            float s = 0.f;
            #pragma unroll
            for (int c = 0; c < HD; c += 4) {
                float4 qv = *(const float4*)(qRow + c);
                float4 kv = *(const float4*)(kRow + c);
                s += qv.x*kv.x + qv.y*kv.y + qv.z*kv.z + qv.w*kv.w;
            }
            s *= 0.125f;  // 1/sqrt(64)
            float mx = s;
            #pragma unroll
            for (int o = 8; o > 0; o >>= 1) mx = fmaxf(mx, __shfl_xor_sync(0xffffffffu, mx, o));
            float ex = expf(s - mx);
            float sum = ex;
            #pragma unroll
            for (int o = 8; o > 0; o >>= 1) sum += __shfl_xor_sync(0xffffffffu, sum, o);
            ss[R*17 + sm] = ex / sum;
        }
    }
    __syncthreads();

    // O = A @ V: 2 threads per row, interleaved col quads; write gmem directly
    {
        const int R = tid >> 1;           // 0..127
        const int nd = R >> 4;
        const int c0 = (tid & 1) * 4;     // cols c0 + 8j
        float4 o4[8];
        #pragma unroll
        for (int j = 0; j < 8; j++) o4[j] = make_float4(0.f, 0.f, 0.f, 0.f);
        #pragma unroll
        for (int m = 0; m < Ln; m++) {
            float w = ss[R*17 + m];
            const float* vRow = sV + (nd*16 + m)*TSTR;
            #pragma unroll
            for (int j = 0; j < 8; j++) {
                float4 vv = *(const float4*)(vRow + c0 + 8*j);
                o4[j].x += w*vv.x; o4[j].y += w*vv.y; o4[j].z += w*vv.z; o4[j].w += w*vv.w;
            }
        }
        float* Orow = O + (size_t)(bm + R)*Ee + bn;
        #pragma unroll
        for (int j = 0; j < 8; j++)
            *(float4*)(Orow + c0 + 8*j) = o4[j];
    }
}

// ---------------- dual tensor-core multi-B GEMM for Kf/Vf ----------------
template<int NMAT>
__global__ void __launch_bounds__(256) gemm_tc_dual(DualArgs p)
{
    constexpr int BM = 128, BK = 32;
    constexpr int ASTR = 36;
    constexpr int BBLK = BK * 64;
    constexpr int NT = Ee / BK;
    extern __shared__ float smp[];
    float* AsBase = smp;
    float* BsBase = smp + 2*BM*ASTR;

    const int z = blockIdx.z;
    const float* __restrict__ A = p.A[z];
    const int* __restrict__ rows = p.rows[z];
    const int out_grp = p.out_grp, out_str = p.out_str, out_off = p.out_off[z];

    const int tid = threadIdx.x;
    const int nb = blockIdx.x;
    const int bm = blockIdx.y * BM;
    const int bn = nb * 64;
    const int warpId = tid >> 5, lane = tid & 31;
    const int wm = (warpId & 3) * 32;
    const int wn2 = warpId >> 2;
    const int wn = wn2 * 32;
    const int g = lane >> 2, t = lane & 3;

    const float* Bp[NMAT]; const float* biasp[NMAT]; float* Cp[NMAT];
    #pragma unroll
    for (int q = 0; q < NMAT; q++) { Bp[q] = p.B[z][q]; biasp[q] = p.bias[z][q]; Cp[q] = p.C[z][q]; }

    float acc[NMAT][2][4][4];
    #pragma unroll
    for (int q = 0; q < NMAT; q++)
        #pragma unroll
        for (int mi = 0; mi < 2; mi++)
            #pragma unroll
            for (int ni = 0; ni < 4; ni++)
                #pragma unroll
                for (int v = 0; v < 4; v++) acc[q][mi][ni][v] = 0.f;

    const int aRow = tid >> 3;
    const int aCol = (tid & 7) * 4;
    size_t gA[4];
    #pragma unroll
    for (int i = 0; i < 4; i++) {
        int m = bm + aRow + i*32;
        gA[i] = (size_t)(rows ? rows[m] : m) * Ee;
    }

    auto issue = [&](int kt, int st) {
        float* As = AsBase + st*BM*ASTR;
        #pragma unroll
        for (int i = 0; i < 4; i++)
            cp_async16(&As[(aRow + i*32)*ASTR + aCol], A + gA[i] + kt*BK + aCol);
        #pragma unroll
        for (int q = 0; q < NMAT; q++) {
            float* Bs = BsBase + (st*NMAT + q)*BBLK;
            const float* src = Bp[q] + (size_t)(kt*5 + nb)*BBLK + tid*8;
            cp_async16(&Bs[tid*8],     src);
            cp_async16(&Bs[tid*8 + 4], src + 4);
        }
    };

    auto compute = [&](int st) {
        const float* As = AsBase + st*BM*ASTR;
        #pragma unroll
        for (int kk = 0; kk < BK; kk += 8) {
            const int kk4 = kk >> 3;
            uint32_t afr[2][4];
            #pragma unroll
            for (int mi = 0; mi < 2; mi++) {
                int r0 = wm + mi*16 + g;
                afr[mi][0] = __float_as_uint(As[(r0    )*ASTR + kk + t    ]);
                afr[mi][1] = __float_as_uint(As[(r0 + 8)*ASTR + kk + t    ]);
                afr[mi][2] = __float_as_uint(As[(r0    )*ASTR + kk + t + 4]);
                afr[mi][3] = __float_as_uint(As[(r0 + 8)*ASTR + kk + t + 4]);
            }
            #pragma unroll
            for (int q = 0; q < NMAT; q++) {
                const float4* Bf = (const float4*)(BsBase + (st*NMAT + q)*BBLK);
                const int base8 = (wn2*4 + kk4)*2;
                float4 fa = Bf[(base8    )*32 + lane];
                float4 fb = Bf[(base8 + 1)*32 + lane];
                #pragma unroll
                for (int mi = 0; mi < 2; mi++) {
                    mma_tf32(acc[q][mi][0], afr[mi], __float_as_uint(fa.x), __float_as_uint(fa.y));
                    mma_tf32(acc[q][mi][1], afr[mi], __float_as_uint(fa.z), __float_as_uint(fa.w));
                    mma_tf32(acc[q][mi][2], afr[mi], __float_as_uint(fb.x), __float_as_uint(fb.y));
                    mma_tf32(acc[q][mi][3], afr[mi], __float_as_uint(fb.z), __float_as_uint(fb.w));
                }
            }
        }
    };

    issue(0, 0);
    cp_commit();

    #pragma unroll 1
    for (int kt = 0; kt < NT; kt++) {
        int st = kt & 1;
        if (kt + 1 < NT) {
            issue(kt + 1, st ^ 1);
            cp_commit();
            asm volatile("cp.async.wait_group 1;" ::: "memory");
        } else {
            asm volatile("cp.async.wait_group 0;" ::: "memory");
        }
        __syncthreads();
        compute(st);
        __syncthreads();
    }

    #pragma unroll
    for (int q = 0; q < NMAT; q++) {
        #pragma unroll
        for (int ni = 0; ni < 4; ni++) {
            int n = bn + wn + ni*8 + 2*t;
            float bb0 = biasp[q][n], bb1 = biasp[q][n+1];
            #pragma unroll
            for (int mi = 0; mi < 2; mi++) {
                int m0 = bm + wm + mi*16 + g;
                int m1 = m0 + 8;
                int cr0 = (m0 / out_grp) * out_str + (m0 % out_grp) + out_off;
                int cr1 = (m1 / out_grp) * out_str + (m1 % out_grp) + out_off;
                float2 v0, v1;
                v0.x = acc[q][mi][ni][0] + bb0; v0.y = acc[q][mi][ni][1] + bb1;
                v1.x = acc[q][mi][ni][2] + bb0; v1.y = acc[q][mi][ni][3] + bb1;
                *(float2*)(Cp[q] + (size_t)cr0*Ee + n) = v0;
                *(float2*)(Cp[q] + (size_t)cr1*Ee + n) = v1;
            }
        }
    }
}

// ---------------- single-B SIMT GEMM with M guard (q0: M = 10000, fp32 exact) ----------------
__global__ void __launch_bounds__(256) gemm320(
    const float* __restrict__ A, const int* __restrict__ rows, int M,
    const float* __restrict__ B, const float* __restrict__ bias,
    float* __restrict__ C)
{
    constexpr int BM = 64, BN = 64, BK = 16;
    __shared__ float As[BK][BM];
    __shared__ float Bs[BK][BN];
    const int tid = threadIdx.x;
    const int bm = blockIdx.y * BM;
    const int bn = blockIdx.x * BN;
    const int tcol = tid & 15;
    const int trow = tid >> 4;

    float acc[4][4];
    #pragma unroll
    for (int i = 0; i < 4; i++)
        #pragma unroll
        for (int j = 0; j < 4; j++) acc[i][j] = 0.f;

    const int aRow = tid >> 2;
    const int aCol = (tid & 3) << 2;
    int r = bm + aRow; if (r >= M) r = M - 1;
    const size_t ga = (size_t)(rows ? rows[r] : r) * Ee;
    const int bRow = tid >> 4;
    const int bCol = (tid & 15) << 2;

    for (int k0 = 0; k0 < Ee; k0 += BK) {
        float4 a4 = *(const float4*)(A + ga + k0 + aCol);
        float4 b4 = *(const float4*)(B + (size_t)(k0 + bRow)*Ee + bn + bCol);
        As[aCol+0][aRow] = a4.x; As[aCol+1][aRow] = a4.y;
        As[aCol+2][aRow] = a4.z; As[aCol+3][aRow] = a4.w;
        *(float4*)&Bs[bRow][bCol] = b4;
        __syncthreads();

        #pragma unroll
        for (int kk = 0; kk < BK; kk++) {
            float ar[4], br[4];
            #pragma unroll
            for (int i = 0; i < 4; i++) ar[i] = As[kk][trow*4 + i];
            #pragma unroll
            for (int j = 0; j < 4; j++) br[j] = Bs[kk][tcol*4 + j];
            #pragma unroll
            for (int i = 0; i < 4; i++)
                #pragma unroll
                for (int j = 0; j < 4; j++)
                    acc[i][j] += ar[i] * br[j];
        }
        __syncthreads();
    }

    float bb[4];
    #pragma unroll
    for (int j = 0; j < 4; j++) bb[j] = bias[bn + tcol*4 + j];
    #pragma unroll
    for (int i = 0; i < 4; i++) {
        int m = bm + trow*4 + i;
        if (m < M) {
            float4 o;
            o.x = acc[i][0] + bb[0];
            o.y = acc[i][1] + bb[1];
            o.z = acc[i][2] + bb[2];
            o.w = acc[i][3] + bb[3];
            *(float4*)(C + (size_t)m*Ee + bn + tcol*4) = o;
        }
    }
}

// ---------------- final 1-head attention over 32 tokens + fused output proj + ELU ----------------
__global__ void __launch_bounds__(256) final_attn(
    const float* __restrict__ q0, const float* __restrict__ Kf,
    const float* __restrict__ Vf, const float* __restrict__ Fmat,
    const float* __restrict__ fbias, float* __restrict__ out)
{
    __shared__ float sqv[Ee];
    __shared__ float sc[32];
    __shared__ float so[Ee];
    const int n = blockIdx.x;
    const int tid = threadIdx.x;
    const int warp = tid >> 5, lane = tid & 31;
    const float scale = 0.05590169943749474f;  // 1/sqrt(320)

    if (tid < Ee/4) {
        ((float4*)sqv)[tid] = ((const float4*)(q0 + (size_t)n*Ee))[tid];
    }
    __syncthreads();

    #pragma unroll
    for (int i = 0; i < 4; i++) {
        int m = warp*4 + i;
        const float4* kr = (const float4*)(Kf + ((size_t)n*32 + m) * Ee);
        float s = 0.f;
        #pragma unroll 1
        for (int f = lane; f < Ee/4; f += 32) {
            float4 kv = kr[f];
            float4 qv = ((const float4*)sqv)[f];
            s += qv.x*kv.x + qv.y*kv.y + qv.z*kv.z + qv.w*kv.w;
        }
        #pragma unroll
        for (int o = 16; o > 0; o >>= 1) s += __shfl_down_sync(0xffffffffu, s, o);
        if (lane == 0) sc[m] = s * scale;
    }
    __syncthreads();

    if (warp == 0) {
        float v = sc[lane];
        float mx = v;
        #pragma unroll
        for (int o = 16; o > 0; o >>= 1) mx = fmaxf(mx, __shfl_xor_sync(0xffffffffu, mx, o));
        float ex = expf(v - mx);
        float sm = ex;
        #pragma unroll
        for (int o = 16; o > 0; o >>= 1) sm += __shfl_xor_sync(0xffffffffu, sm, o);
        sc[lane] = ex / sm;
    }
    __syncthreads();

    for (int e = tid; e < Ee; e += 256) {
        const float* vr = Vf + (size_t)n*32*Ee + e;
        float a = 0.f;
        #pragma unroll
        for (int m = 0; m < 32; m++) a += sc[m] * vr[(size_t)m*Ee];
        so[e] = a;
    }
    __syncthreads();

    #pragma unroll
    for (int i = 0; i < 4; i++) {
        int j = warp*4 + i;
        if (j < OUTD) {
            float s = 0.f;
            for (int e = lane; e < Ee; e += 32) s += so[e] * Fmat[(size_t)e*OUTD + j];
            #pragma unroll
            for (int o = 16; o > 0; o >>= 1) s += __shfl_down_sync(0xffffffffu, s, o);
            if (lane == 0) {
                float x = s + fbias[j];
                out[(size_t)n*OUTD + j] = x > 0.f ? x : expm1f(x);
            }
        }
    }
}

// ---------------- host ----------------
#define GETSYM(p, s) do { void* _t; cudaGetSymbolAddress(&_t, s); p = decltype(p)(_t); } while (0)

extern "C" void kernel_launch(void* const* d_in, const int* in_sizes, int n_in,
                              void* d_out, int out_size)
{
    const float* X        = (const float*)d_in[0];
    const int*   in_idx   = (const int*)  d_in[1];
    const int*   out_idx  = (const int*)  d_in[2];
    const float* in_Wq    = (const float*)d_in[3];
    const float* in_Wk    = (const float*)d_in[4];
    const float* in_Wv    = (const float*)d_in[5];
    const float* in_qkv_w = (const float*)d_in[6];
    const float* in_qkv_b = (const float*)d_in[7];
    const float* in_o_w   = (const float*)d_in[8];
    const float* in_o_b   = (const float*)d_in[9];
    const float* out_Wq   = (const float*)d_in[10];
    const float* out_Wk   = (const float*)d_in[11];
    const float* out_Wv   = (const float*)d_in[12];
    const float* out_qkv_w= (const float*)d_in[13];
    const float* out_qkv_b= (const float*)d_in[14];
    const float* out_o_w  = (const float*)d_in[15];
    const float* out_o_b  = (const float*)d_in[16];
    const float* fin_qkv_w= (const float*)d_in[17];
    const float* fin_qkv_b= (const float*)d_in[18];
    const float* fin_o_w  = (const float*)d_in[19];
    const float* fin_o_b  = (const float*)d_in[20];
    const float* Wfin     = (const float*)d_in[21];
    float* out = (float*)d_out;

    float *Mq_in, *Mk_in, *Mv_in, *Mq_out, *Mk_out, *Mv_out;
    float *Qmat, *Kmat_in, *Kmat_out, *Vmat_in, *Vmat_out;
    float *T_in_o, *T_out_o, *T_fin_o;
    float *qbias, *kbias_in, *kbias_out, *vbias_in, *vbias_out;
    float *Fmat, *fbias, *Oin, *Oout, *Kf, *Vf, *q0;
    int *rows_in, *rows_out, *rows_q0;
    GETSYM(Mq_in, g_Mq_in);   GETSYM(Mk_in, g_Mk_in);   GETSYM(Mv_in, g_Mv_in);
    GETSYM(Mq_out, g_Mq_out); GETSYM(Mk_out, g_Mk_out); GETSYM(Mv_out, g_Mv_out);
    GETSYM(Qmat, g_Qmat);     GETSYM(Kmat_in, g_Kmat_in); GETSYM(Kmat_out, g_Kmat_out);
    GETSYM(Vmat_in, g_Vmat_in); GETSYM(Vmat_out, g_Vmat_out);
    GETSYM(T_in_o, g_T_in_o); GETSYM(T_out_o, g_T_out_o); GETSYM(T_fin_o, g_T_fin_o);
    GETSYM(qbias, g_qbias);   GETSYM(kbias_in, g_kbias_in); GETSYM(kbias_out, g_kbias_out);
    GETSYM(vbias_in, g_vbias_in); GETSYM(vbias_out, g_vbias_out);
    GETSYM(Fmat, g_Fmat);     GETSYM(fbias, g_fbias);
    GETSYM(Oin, g_Oin); GETSYM(Oout, g_Oout);
    GETSYM(Kf, g_Kf); GETSYM(Vf, g_Vf); GETSYM(q0, g_q0);
    GETSYM(rows_in, g_rows_in); GETSYM(rows_out, g_rows_out); GETSYM(rows_q0, g_rows_q0);

    const int CB = 256;

    // smem: fused kernel needs max(pipeline 86016, attention tiles (3*128*68+128*17)*4 = 113024)
    const int SMEM_FUSED = (3*128*68 + 128*17) * 4;      // 113024
    const int SMEM2 = (2*128*36 + 2*2*2048) * 4;         // 69632
    cudaFuncSetAttribute(gemm_attn_dual,  cudaFuncAttributeMaxDynamicSharedMemorySize, SMEM_FUSED);
    cudaFuncSetAttribute(gemm_tc_dual<2>, cudaFuncAttributeMaxDynamicSharedMemorySize, SMEM2);

    // 1) row gather tables + transposes of the three output-proj matrices
    build_rows<<<(Nn + CB - 1)/CB, CB>>>(in_idx, out_idx, rows_in, rows_out, rows_q0);
    dim3 tG(10, 10), tB(32, 8);
    transpose320<<<tG, tB>>>(in_o_w,  T_in_o);
    transpose320<<<tG, tB>>>(out_o_w, T_out_o);
    transpose320<<<tG, tB>>>(fin_o_w, T_fin_o);

    // 2+3) all 11 combined matrices in ONE batched launch: C = A @ B^T
    CombineBatch cb;
    cb.A[0] = in_Wq;   cb.B[0] = in_qkv_w;            cb.C[0] = Mq_in;    cb.perm[0] = 1;
    cb.A[1] = in_Wk;   cb.B[1] = in_qkv_w + Ee*Ee;    cb.C[1] = Mk_in;    cb.perm[1] = 1;
    cb.A[2] = in_Wv;   cb.B[2] = in_qkv_w + 2*Ee*Ee;  cb.C[2] = Mv_in;    cb.perm[2] = 1;
    cb.A[3] = out_Wq;  cb.B[3] = out_qkv_w;           cb.C[3] = Mq_out;   cb.perm[3] = 1;
    cb.A[4] = out_Wk;  cb.B[4] = out_qkv_w + Ee*Ee;   cb.C[4] = Mk_out;   cb.perm[4] = 1;
    cb.A[5] = out_Wv;  cb.B[5] = out_qkv_w + 2*Ee*Ee; cb.C[5] = Mv_out;   cb.perm[5] = 1;
    cb.A[6] = T_in_o;  cb.B[6] = fin_qkv_w;           cb.C[6] = Qmat;     cb.perm[6] = 0;
    cb.A[7] = T_in_o;  cb.B[7] = fin_qkv_w + Ee*Ee;   cb.C[7] = Kmat_in;  cb.perm[7] = 1;
    cb.A[8] = T_out_o; cb.B[8] = fin_qkv_w + Ee*Ee;   cb.C[8] = Kmat_out; cb.perm[8] = 1;
    cb.A[9] = T_in_o;  cb.B[9] = fin_qkv_w + 2*Ee*Ee; cb.C[9] = Vmat_in;  cb.perm[9] = 1;
    cb.A[10]= T_out_o; cb.B[10]= fin_qkv_w + 2*Ee*Ee; cb.C[10]= Vmat_out; cb.perm[10]= 1;
    combine_batch<<<dim3(5, 5, NCOMB), CB>>>(cb);

    BiasBatch bb;
    bb.bo[0] = in_o_b;  bb.Bq[0] = fin_qkv_w;           bb.b2[0] = fin_qkv_b;          bb.out[0] = qbias;
    bb.bo[1] = in_o_b;  bb.Bq[1] = fin_qkv_w + Ee*Ee;   bb.b2[1] = fin_qkv_b + Ee;     bb.out[1] = kbias_in;
    bb.bo[2] = out_o_b; bb.Bq[2] = fin_qkv_w + Ee*Ee;   bb.b2[2] = fin_qkv_b + Ee;     bb.out[2] = kbias_out;
    bb.bo[3] = in_o_b;  bb.Bq[3] = fin_qkv_w + 2*Ee*Ee; bb.b2[3] = fin_qkv_b + 2*Ee;   bb.out[3] = vbias_in;
    bb.bo[4] = out_o_b; bb.Bq[4] = fin_qkv_w + 2*Ee*Ee; bb.b2[4] = fin_qkv_b + 2*Ee;   bb.out[4] = vbias_out;
    bias_batch<<<dim3(40, NBIAS), CB>>>(bb);

    // 4) fold final output-proj into readout: Fmat = wof.T @ W
    combine_fmat_w<<<(Ee*OUTD + 7)/8, CB>>>(T_fin_o, Wfin, Fmat);
    combine_fbias_w<<<1, CB>>>(fin_o_b, Wfin, fbias);

    const int Mfull = Nn * Ln;           // 160000 = 1250 * 128

    // 5+6) BOTH layers: fused QKV-GEMM + attention, writing Oin/Oout directly
    DualArgs d3;
    d3.A[0] = X;  d3.A[1] = X;
    d3.rows[0] = rows_in;  d3.rows[1] = rows_out;
    d3.B[0][0] = Mq_in;  d3.B[0][1] = Mk_in;  d3.B[0][2] = Mv_in;
    d3.B[1][0] = Mq_out; d3.B[1][1] = Mk_out; d3.B[1][2] = Mv_out;
    d3.bias[0][0] = in_qkv_b;  d3.bias[0][1] = in_qkv_b + Ee;  d3.bias[0][2] = in_qkv_b + 2*Ee;
    d3.bias[1][0] = out_qkv_b; d3.bias[1][1] = out_qkv_b + Ee; d3.bias[1][2] = out_qkv_b + 2*Ee;
    d3.C[0][0] = Oin;  d3.C[0][1] = nullptr; d3.C[0][2] = nullptr;
    d3.C[1][0] = Oout; d3.C[1][1] = nullptr; d3.C[1][2] = nullptr;
    d3.out_grp = 16; d3.out_str = 16; d3.out_off[0] = 0; d3.out_off[1] = 0;
    gemm_attn_dual<<<dim3(Ee/64, Mfull/128, 2), 256, SMEM_FUSED>>>(d3);

    // 7) final-layer K/V: both sources in one dual launch (interleaved halves)
    DualArgs d2;
    d2.A[0] = Oin;  d2.A[1] = Oout;
    d2.rows[0] = nullptr; d2.rows[1] = nullptr;
    d2.B[0][0] = Kmat_in;  d2.B[0][1] = Vmat_in;  d2.B[0][2] = nullptr;
    d2.B[1][0] = Kmat_out; d2.B[1][1] = Vmat_out; d2.B[1][2] = nullptr;
    d2.bias[0][0] = kbias_in;  d2.bias[0][1] = vbias_in;  d2.bias[0][2] = nullptr;
    d2.bias[1][0] = kbias_out; d2.bias[1][1] = vbias_out; d2.bias[1][2] = nullptr;
    d2.C[0][0] = Kf; d2.C[0][1] = Vf; d2.C[0][2] = nullptr;
    d2.C[1][0] = Kf; d2.C[1][1] = Vf; d2.C[1][2] = nullptr;
    d2.out_grp = 16; d2.out_str = 32; d2.out_off[0] = 0; d2.out_off[1] = 16;
    gemm_tc_dual<2><<<dim3(Ee/64, Mfull/128, 2), 256, SMEM2>>>(d2);

    gemm320<<<dim3(Ee/64, (Nn + 63)/64), 256>>>(Oin, rows_q0, Nn, Qmat, qbias, q0);

    // 8) final attention + fused readout + ELU
    final_attn<<<Nn, 256>>>(q0, Kf, Vf, Fmat, fbias, out);
}

// round 17
// speedup vs baseline: 1.4521x; 1.1254x over previous
#include <cuda_runtime.h>
#include <math.h>
#include <stdint.h>

#define Nn 10000
#define Dn 15
#define Ln 16
#define Ee 320
#define OUTD 30
#define NH 5
#define HD 64

// ---------------- scratch (static device globals; no allocation) ----------------
__device__ float g_Mq_in[Ee*Ee], g_Mk_in[Ee*Ee], g_Mv_in[Ee*Ee];
__device__ float g_Mq_out[Ee*Ee], g_Mk_out[Ee*Ee], g_Mv_out[Ee*Ee];
__device__ float g_Qmat[Ee*Ee], g_Kmat_in[Ee*Ee], g_Kmat_out[Ee*Ee];
__device__ float g_Vmat_in[Ee*Ee], g_Vmat_out[Ee*Ee];
__device__ float g_S_in[Ee*Ee], g_S_out[Ee*Ee];
__device__ float g_T_in_o[Ee*Ee], g_T_out_o[Ee*Ee], g_T_fin_o[Ee*Ee];
__device__ float g_qbias[Ee], g_kbias_in[Ee], g_kbias_out[Ee], g_vbias_in[Ee], g_vbias_out[Ee];
__device__ float g_v1_in[Ee], g_v1_out[Ee], g_v2_in[Ee], g_v2_out[Ee];
__device__ float g_zeroE[Ee];   // stays zero (device globals are zero-initialized, never written)
__device__ float g_Fmat[Ee*OUTD], g_fbias[OUTD];
__device__ int   g_rows_in[Nn*Ln], g_rows_out[Nn*Ln], g_rows_q0[Nn];
__device__ float g_Oin[(size_t)Nn*Ln*Ee], g_Oout[(size_t)Nn*Ln*Ee];
__device__ float g_Vf[(size_t)Nn*2*Ln*Ee];
__device__ float g_z_in[(size_t)Nn*Ee], g_z_out[(size_t)Nn*Ee];
__device__ float g_s0_in[Nn], g_s0_out[Nn];

// ---------------- helpers ----------------
__device__ __forceinline__ void mma_tf32(float* d, const uint32_t* a, uint32_t b0, uint32_t b1) {
    asm volatile(
        "mma.sync.aligned.m16n8k8.row.col.f32.tf32.tf32.f32 "
        "{%0,%1,%2,%3}, {%4,%5,%6,%7}, {%8,%9}, {%0,%1,%2,%3};"
        : "+f"(d[0]), "+f"(d[1]), "+f"(d[2]), "+f"(d[3])
        : "r"(a[0]), "r"(a[1]), "r"(a[2]), "r"(a[3]), "r"(b0), "r"(b1));
}

__device__ __forceinline__ void cp_async16(void* smem_dst, const void* gmem_src) {
    uint32_t d = (uint32_t)__cvta_generic_to_shared(smem_dst);
    asm volatile("cp.async.cg.shared.global [%0], [%1], 16;" :: "r"(d), "l"(gmem_src));
}
__device__ __forceinline__ void cp_commit() {
    asm volatile("cp.async.commit_group;" ::: "memory");
}

// Permuted (MMA-fragment-order) address for weight matrices consumed by the tc GEMMs.
__device__ __forceinline__ size_t perm_addr(int k, int n) {
    int kt = k >> 5, kin = k & 31;
    int kk4 = kin >> 3, c4 = (kin >> 2) & 1, t = kin & 3;
    int nb = n >> 6, nin = n & 63;
    int wn2 = nin >> 5, ni = (nin >> 3) & 3, g = nin & 7;
    int lane = g*4 + t;
    int f4i = ni >> 1, comp = ((ni & 1) << 1) + c4;
    return (size_t)(kt*5 + nb)*2048 + (size_t)(((wn2*4 + kk4)*2 + f4i)*128 + lane*4 + comp);
}

// ---------------- precompute kernels ----------------

__global__ void transpose320(const float* __restrict__ in, float* __restrict__ out) {
    __shared__ float tile[32][33];
    int bx = blockIdx.x * 32, by = blockIdx.y * 32;
    int x = bx + threadIdx.x;
    #pragma unroll
    for (int i = 0; i < 32; i += 8) {
        int y = by + threadIdx.y + i;
        tile[threadIdx.y + i][threadIdx.x] = in[(size_t)y*Ee + x];
    }
    __syncthreads();
    x = by + threadIdx.x;
    #pragma unroll
    for (int i = 0; i < 32; i += 8) {
        int y = bx + threadIdx.y + i;
        out[(size_t)y*Ee + x] = tile[threadIdx.x][threadIdx.y + i];
    }
}

#define NCOMB 11
struct CombineBatch {
    const float* A[NCOMB];
    const float* B[NCOMB];
    float*       C[NCOMB];
    int          perm[NCOMB];
};
__global__ void __launch_bounds__(256) combine_batch(CombineBatch p) {
    const float* __restrict__ A = p.A[blockIdx.z];
    const float* __restrict__ B = p.B[blockIdx.z];
    float* __restrict__ C = p.C[blockIdx.z];
    const int doperm = p.perm[blockIdx.z];
    constexpr int BK = 16;
    __shared__ float As[BK][64];
    __shared__ float Bs[BK][64];
    const int tid = threadIdx.x;
    const int bm = blockIdx.y * 64;
    const int bn = blockIdx.x * 64;
    const int tcol = tid & 15, trow = tid >> 4;
    const int aRow = tid >> 2, aCol = (tid & 3) << 2;

    float acc[4][4];
    #pragma unroll
    for (int i = 0; i < 4; i++)
        #pragma unroll
        for (int j = 0; j < 4; j++) acc[i][j] = 0.f;

    for (int k0 = 0; k0 < Ee; k0 += BK) {
        float4 a4 = *(const float4*)(A + (size_t)(bm + aRow)*Ee + k0 + aCol);
        float4 b4 = *(const float4*)(B + (size_t)(bn + aRow)*Ee + k0 + aCol);
        As[aCol+0][aRow] = a4.x; As[aCol+1][aRow] = a4.y;
        As[aCol+2][aRow] = a4.z; As[aCol+3][aRow] = a4.w;
        Bs[aCol+0][aRow] = b4.x; Bs[aCol+1][aRow] = b4.y;
        Bs[aCol+2][aRow] = b4.z; Bs[aCol+3][aRow] = b4.w;
        __syncthreads();
        #pragma unroll
        for (int kk = 0; kk < BK; kk++) {
            float ar[4], br[4];
            #pragma unroll
            for (int i = 0; i < 4; i++) ar[i] = As[kk][trow*4 + i];
            #pragma unroll
            for (int j = 0; j < 4; j++) br[j] = Bs[kk][tcol*4 + j];
            #pragma unroll
            for (int i = 0; i < 4; i++)
                #pragma unroll
                for (int j = 0; j < 4; j++)
                    acc[i][j] += ar[i] * br[j];
        }
        __syncthreads();
    }
    if (doperm) {
        #pragma unroll
        for (int i = 0; i < 4; i++)
            #pragma unroll
            for (int j = 0; j < 4; j++)
                C[perm_addr(bm + trow*4 + i, bn + tcol*4 + j)] = acc[i][j];
    } else {
        #pragma unroll
        for (int i = 0; i < 4; i++)
            #pragma unroll
            for (int j = 0; j < 4; j++)
                C[(size_t)(bm + trow*4 + i)*Ee + bn + tcol*4 + j] = acc[i][j];
    }
}

#define NBIAS 5
struct BiasBatch {
    const float* bo[NBIAS];
    const float* Bq[NBIAS];
    const float* b2[NBIAS];
    float*       out[NBIAS];
};
__global__ void __launch_bounds__(256) bias_batch(BiasBatch p) {
    int task = blockIdx.y;
    const float* __restrict__ bo = p.bo[task];
    const float* __restrict__ Bq = p.Bq[task];
    int j = (blockIdx.x * 256 + threadIdx.x) >> 5;
    int lane = threadIdx.x & 31;
    if (j >= Ee) return;
    const float* br = Bq + (size_t)j*Ee;
    float s = 0.f;
    #pragma unroll
    for (int e = lane, i = 0; i < Ee/32; e += 32, i++) s += bo[e] * br[e];
    #pragma unroll
    for (int off = 16; off > 0; off >>= 1) s += __shfl_down_sync(0xffffffffu, s, off);
    if (lane == 0) p.out[task][j] = s + p.b2[task][j];
}

__global__ void combine_fmat_w(const float* __restrict__ fowT, const float* __restrict__ W,
                               float* __restrict__ out) {
    int o = (blockIdx.x * 256 + threadIdx.x) >> 5;
    int lane = threadIdx.x & 31;
    if (o >= Ee*OUTD) return;
    int e = o / OUTD, j = o % OUTD;
    const float* fr = fowT + (size_t)e*Ee;
    float s = 0.f;
    #pragma unroll
    for (int t = lane, i = 0; i < Ee/32; t += 32, i++) s += fr[t] * W[(size_t)t*OUTD + j];
    #pragma unroll
    for (int off = 16; off > 0; off >>= 1) s += __shfl_down_sync(0xffffffffu, s, off);
    if (lane == 0) out[o] = s;
}

__global__ void combine_fbias_w(const float* __restrict__ fob, const float* __restrict__ W,
                                float* __restrict__ out) {
    int warp = threadIdx.x >> 5, lane = threadIdx.x & 31;
    for (int j = warp; j < OUTD; j += 8) {
        float s = 0.f;
        #pragma unroll
        for (int t = lane, i = 0; i < Ee/32; t += 32, i++) s += fob[t] * W[(size_t)t*OUTD + j];
        #pragma unroll
        for (int off = 16; off > 0; off >>= 1) s += __shfl_down_sync(0xffffffffu, s, off);
        if (lane == 0) out[j] = s;
    }
}

__global__ void build_rows(const int* __restrict__ in_idx, const int* __restrict__ out_idx,
                           int* __restrict__ rin, int* __restrict__ rout, int* __restrict__ rq0) {
    int n = blockIdx.x * blockDim.x + threadIdx.x;
    if (n >= Nn) return;
    rin[n*Ln] = n;
    rout[n*Ln] = n;
    rq0[n] = n*Ln;
    #pragma unroll
    for (int d = 0; d < Dn; d++) {
        rin[n*Ln + 1 + d]  = in_idx[n*Dn + d];
        rout[n*Ln + 1 + d] = out_idx[n*Dn + d];
    }
}

// s0[n] = Oin[n*16]·v1 + qbias·kbias (per half). One warp per node.
__global__ void __launch_bounds__(256) s0_kernel(
    const float* __restrict__ Oin,
    const float* __restrict__ v1_in, const float* __restrict__ v1_out,
    const float* __restrict__ qbias,
    const float* __restrict__ kbias_in, const float* __restrict__ kbias_out,
    float* __restrict__ s0_in, float* __restrict__ s0_out)
{
    int n = (blockIdx.x * 256 + threadIdx.x) >> 5;
    int lane = threadIdx.x & 31;
    if (n >= Nn) return;
    const float* a = Oin + (size_t)n*Ln*Ee;   // row n*16
    float si = 0.f, so = 0.f, ci = 0.f, co = 0.f;
    #pragma unroll
    for (int e = lane, i = 0; i < Ee/32; e += 32, i++) {
        float av = a[e], qb = qbias[e];
        si += av * v1_in[e];
        so += av * v1_out[e];
        ci += qb * kbias_in[e];
        co += qb * kbias_out[e];
    }
    #pragma unroll
    for (int off = 16; off > 0; off >>= 1) {
        si += __shfl_down_sync(0xffffffffu, si, off);
        so += __shfl_down_sync(0xffffffffu, so, off);
        ci += __shfl_down_sync(0xffffffffu, ci, off);
        co += __shfl_down_sync(0xffffffffu, co, off);
    }
    if (lane == 0) { s0_in[n] = si + ci; s0_out[n] = so + co; }
}

// ---------------- args structs ----------------
struct DualArgs {
    const float* A[2];
    const int*   rows[2];
    const float* B[2][3];
    const float* bias[2][3];
    float*       C[2][3];
    int out_grp, out_str;
    int out_off[2];
};

// ================= FUSED QKV GEMM + 5-head attention (grid.z selects layer) =================
__global__ void __launch_bounds__(256) gemm_attn_dual(DualArgs p)
{
    constexpr int BM = 128, BK = 32;
    constexpr int ASTR = 36;
    constexpr int BBLK = BK * 64;
    constexpr int NT = Ee / BK;
    constexpr int TSTR = 68;        // 272B row stride, 16B-aligned
    extern __shared__ float smp[];
    float* AsBase = smp;
    float* BsBase = smp + 2*BM*ASTR;

    const int z = blockIdx.z;
    const float* __restrict__ A = p.A[z];
    const int* __restrict__ rows = p.rows[z];

    const int tid = threadIdx.x;
    const int nb = blockIdx.x;
    const int bm = blockIdx.y * BM;
    const int bn = nb * 64;
    const int warpId = tid >> 5, lane = tid & 31;
    const int wm = (warpId & 3) * 32;
    const int wn2 = warpId >> 2;
    const int wn = wn2 * 32;
    const int g = lane >> 2, t = lane & 3;

    const float* Bp[3]; const float* biasp[3];
    #pragma unroll
    for (int q = 0; q < 3; q++) { Bp[q] = p.B[z][q]; biasp[q] = p.bias[z][q]; }
    float* __restrict__ O = p.C[z][0];

    float acc[3][2][4][4];
    #pragma unroll
    for (int q = 0; q < 3; q++)
        #pragma unroll
        for (int mi = 0; mi < 2; mi++)
            #pragma unroll
            for (int ni = 0; ni < 4; ni++)
                #pragma unroll
                for (int v = 0; v < 4; v++) acc[q][mi][ni][v] = 0.f;

    const int aRow = tid >> 3;
    const int aCol = (tid & 7) * 4;
    size_t gA[4];
    #pragma unroll
    for (int i = 0; i < 4; i++) {
        int m = bm + aRow + i*32;
        gA[i] = (size_t)rows[m] * Ee;
    }

    auto issue = [&](int kt, int st) {
        float* As = AsBase + st*BM*ASTR;
        #pragma unroll
        for (int i = 0; i < 4; i++)
            cp_async16(&As[(aRow + i*32)*ASTR + aCol], A + gA[i] + kt*BK + aCol);
        #pragma unroll
        for (int q = 0; q < 3; q++) {
            float* Bs = BsBase + (st*3 + q)*BBLK;
            const float* src = Bp[q] + (size_t)(kt*5 + nb)*BBLK + tid*8;
            cp_async16(&Bs[tid*8],     src);
            cp_async16(&Bs[tid*8 + 4], src + 4);
        }
    };

    auto compute = [&](int st) {
        const float* As = AsBase + st*BM*ASTR;
        #pragma unroll
        for (int kk = 0; kk < BK; kk += 8) {
            const int kk4 = kk >> 3;
            uint32_t afr[2][4];
            #pragma unroll
            for (int mi = 0; mi < 2; mi++) {
                int r0 = wm + mi*16 + g;
                afr[mi][0] = __float_as_uint(As[(r0    )*ASTR + kk + t    ]);
                afr[mi][1] = __float_as_uint(As[(r0 + 8)*ASTR + kk + t    ]);
                afr[mi][2] = __float_as_uint(As[(r0    )*ASTR + kk + t + 4]);
                afr[mi][3] = __float_as_uint(As[(r0 + 8)*ASTR + kk + t + 4]);
            }
            #pragma unroll
            for (int q = 0; q < 3; q++) {
                const float4* Bf = (const float4*)(BsBase + (st*3 + q)*BBLK);
                const int base8 = (wn2*4 + kk4)*2;
                float4 fa = Bf[(base8    )*32 + lane];
                float4 fb = Bf[(base8 + 1)*32 + lane];
                #pragma unroll
                for (int mi = 0; mi < 2; mi++) {
                    mma_tf32(acc[q][mi][0], afr[mi], __float_as_uint(fa.x), __float_as_uint(fa.y));
                    mma_tf32(acc[q][mi][1], afr[mi], __float_as_uint(fa.z), __float_as_uint(fa.w));
                    mma_tf32(acc[q][mi][2], afr[mi], __float_as_uint(fb.x), __float_as_uint(fb.y));
                    mma_tf32(acc[q][mi][3], afr[mi], __float_as_uint(fb.z), __float_as_uint(fb.w));
                }
            }
        }
    };

    issue(0, 0);
    cp_commit();

    #pragma unroll 1
    for (int kt = 0; kt < NT; kt++) {
        int st = kt & 1;
        if (kt + 1 < NT) {
            issue(kt + 1, st ^ 1);
            cp_commit();
            asm volatile("cp.async.wait_group 1;" ::: "memory");
        } else {
            asm volatile("cp.async.wait_group 0;" ::: "memory");
        }
        __syncthreads();
        compute(st);
        __syncthreads();
    }

    // ---- fused attention epilogue ----
    float* sQ = smp;
    float* sK = smp + 128*TSTR;
    float* sV = smp + 2*128*TSTR;
    float* ss = smp + 3*128*TSTR;

    #pragma unroll
    for (int q = 0; q < 3; q++) {
        float* sX = smp + q*128*TSTR;
        #pragma unroll
        for (int ni = 0; ni < 4; ni++) {
            int c = wn + ni*8 + 2*t;
            float bb0 = biasp[q][bn + c], bb1 = biasp[q][bn + c + 1];
            #pragma unroll
            for (int mi = 0; mi < 2; mi++) {
                int r0 = wm + mi*16 + g;
                sX[r0*TSTR + c]         = acc[q][mi][ni][0] + bb0;
                sX[r0*TSTR + c + 1]     = acc[q][mi][ni][1] + bb1;
                sX[(r0+8)*TSTR + c]     = acc[q][mi][ni][2] + bb0;
                sX[(r0+8)*TSTR + c + 1] = acc[q][mi][ni][3] + bb1;
            }
        }
    }
    __syncthreads();

    {
        const int hw = tid >> 4;
        const int nd = hw >> 1;
        const int sm = tid & 15;
        const int slbase = (hw & 1) * 8;
        const float* kRow = sK + (nd*16 + sm)*TSTR;
        #pragma unroll
        for (int i = 0; i < 8; i++) {
            int R = nd*16 + slbase + i;
            const float* qRow = sQ + R*TSTR;
            float s = 0.f;
            #pragma unroll
            for (int c = 0; c < HD; c += 4) {
                float4 qv = *(const float4*)(qRow + c);
                float4 kv = *(const float4*)(kRow + c);
                s += qv.x*kv.x + qv.y*kv.y + qv.z*kv.z + qv.w*kv.w;
            }
            s *= 0.125f;
            float mx = s;
            #pragma unroll
            for (int o = 8; o > 0; o >>= 1) mx = fmaxf(mx, __shfl_xor_sync(0xffffffffu, mx, o));
            float ex = expf(s - mx);
            float sum = ex;
            #pragma unroll
            for (int o = 8; o > 0; o >>= 1) sum += __shfl_xor_sync(0xffffffffu, sum, o);
            ss[R*17 + sm] = ex / sum;
        }
    }
    __syncthreads();

    {
        const int R = tid >> 1;
        const int nd = R >> 4;
        const int c0 = (tid & 1) * 4;
        float4 o4[8];
        #pragma unroll
        for (int j = 0; j < 8; j++) o4[j] = make_float4(0.f, 0.f, 0.f, 0.f);
        #pragma unroll
        for (int m = 0; m < Ln; m++) {
            float w = ss[R*17 + m];
            const float* vRow = sV + (nd*16 + m)*TSTR;
            #pragma unroll
            for (int j = 0; j < 8; j++) {
                float4 vv = *(const float4*)(vRow + c0 + 8*j);
                o4[j].x += w*vv.x; o4[j].y += w*vv.y; o4[j].z += w*vv.z; o4[j].w += w*vv.w;
            }
        }
        float* Orow = O + (size_t)(bm + R)*Ee + bn;
        #pragma unroll
        for (int j = 0; j < 8; j++)
            *(float4*)(Orow + c0 + 8*j) = o4[j];
    }
}

// ---------------- dual tensor-core multi-B GEMM (used for Vf, NMAT=1) ----------------
template<int NMAT>
__global__ void __launch_bounds__(256) gemm_tc_dual(DualArgs p)
{
    constexpr int BM = 128, BK = 32;
    constexpr int ASTR = 36;
    constexpr int BBLK = BK * 64;
    constexpr int NT = Ee / BK;
    extern __shared__ float smp[];
    float* AsBase = smp;
    float* BsBase = smp + 2*BM*ASTR;

    const int z = blockIdx.z;
    const float* __restrict__ A = p.A[z];
    const int* __restrict__ rows = p.rows[z];
    const int out_grp = p.out_grp, out_str = p.out_str, out_off = p.out_off[z];

    const int tid = threadIdx.x;
    const int nb = blockIdx.x;
    const int bm = blockIdx.y * BM;
    const int bn = nb * 64;
    const int warpId = tid >> 5, lane = tid & 31;
    const int wm = (warpId & 3) * 32;
    const int wn2 = warpId >> 2;
    const int wn = wn2 * 32;
    const int g = lane >> 2, t = lane & 3;

    const float* Bp[NMAT]; const float* biasp[NMAT]; float* Cp[NMAT];
    #pragma unroll
    for (int q = 0; q < NMAT; q++) { Bp[q] = p.B[z][q]; biasp[q] = p.bias[z][q]; Cp[q] = p.C[z][q]; }

    float acc[NMAT][2][4][4];
    #pragma unroll
    for (int q = 0; q < NMAT; q++)
        #pragma unroll
        for (int mi = 0; mi < 2; mi++)
            #pragma unroll
            for (int ni = 0; ni < 4; ni++)
                #pragma unroll
                for (int v = 0; v < 4; v++) acc[q][mi][ni][v] = 0.f;

    const int aRow = tid >> 3;
    const int aCol = (tid & 7) * 4;
    size_t gA[4];
    #pragma unroll
    for (int i = 0; i < 4; i++) {
        int m = bm + aRow + i*32;
        gA[i] = (size_t)(rows ? rows[m] : m) * Ee;
    }

    auto issue = [&](int kt, int st) {
        float* As = AsBase + st*BM*ASTR;
        #pragma unroll
        for (int i = 0; i < 4; i++)
            cp_async16(&As[(aRow + i*32)*ASTR + aCol], A + gA[i] + kt*BK + aCol);
        #pragma unroll
        for (int q = 0; q < NMAT; q++) {
            float* Bs = BsBase + (st*NMAT + q)*BBLK;
            const float* src = Bp[q] + (size_t)(kt*5 + nb)*BBLK + tid*8;
            cp_async16(&Bs[tid*8],     src);
            cp_async16(&Bs[tid*8 + 4], src + 4);
        }
    };

    auto compute = [&](int st) {
        const float* As = AsBase + st*BM*ASTR;
        #pragma unroll
        for (int kk = 0; kk < BK; kk += 8) {
            const int kk4 = kk >> 3;
            uint32_t afr[2][4];
            #pragma unroll
            for (int mi = 0; mi < 2; mi++) {
                int r0 = wm + mi*16 + g;
                afr[mi][0] = __float_as_uint(As[(r0    )*ASTR + kk + t    ]);
                afr[mi][1] = __float_as_uint(As[(r0 + 8)*ASTR + kk + t    ]);
                afr[mi][2] = __float_as_uint(As[(r0    )*ASTR + kk + t + 4]);
                afr[mi][3] = __float_as_uint(As[(r0 + 8)*ASTR + kk + t + 4]);
            }
            #pragma unroll
            for (int q = 0; q < NMAT; q++) {
                const float4* Bf = (const float4*)(BsBase + (st*NMAT + q)*BBLK);
                const int base8 = (wn2*4 + kk4)*2;
                float4 fa = Bf[(base8    )*32 + lane];
                float4 fb = Bf[(base8 + 1)*32 + lane];
                #pragma unroll
                for (int mi = 0; mi < 2; mi++) {
                    mma_tf32(acc[q][mi][0], afr[mi], __float_as_uint(fa.x), __float_as_uint(fa.y));
                    mma_tf32(acc[q][mi][1], afr[mi], __float_as_uint(fa.z), __float_as_uint(fa.w));
                    mma_tf32(acc[q][mi][2], afr[mi], __float_as_uint(fb.x), __float_as_uint(fb.y));
                    mma_tf32(acc[q][mi][3], afr[mi], __float_as_uint(fb.z), __float_as_uint(fb.w));
                }
            }
        }
    };

    issue(0, 0);
    cp_commit();

    #pragma unroll 1
    for (int kt = 0; kt < NT; kt++) {
        int st = kt & 1;
        if (kt + 1 < NT) {
            issue(kt + 1, st ^ 1);
            cp_commit();
            asm volatile("cp.async.wait_group 1;" ::: "memory");
        } else {
            asm volatile("cp.async.wait_group 0;" ::: "memory");
        }
        __syncthreads();
        compute(st);
        __syncthreads();
    }

    #pragma unroll
    for (int q = 0; q < NMAT; q++) {
        #pragma unroll
        for (int ni = 0; ni < 4; ni++) {
            int n = bn + wn + ni*8 + 2*t;
            float bb0 = biasp[q][n], bb1 = biasp[q][n+1];
            #pragma unroll
            for (int mi = 0; mi < 2; mi++) {
                int m0 = bm + wm + mi*16 + g;
                int m1 = m0 + 8;
                int cr0 = (m0 / out_grp) * out_str + (m0 % out_grp) + out_off;
                int cr1 = (m1 / out_grp) * out_str + (m1 % out_grp) + out_off;
                float2 v0, v1;
                v0.x = acc[q][mi][ni][0] + bb0; v0.y = acc[q][mi][ni][1] + bb1;
                v1.x = acc[q][mi][ni][2] + bb0; v1.y = acc[q][mi][ni][3] + bb1;
                *(float2*)(Cp[q] + (size_t)cr0*Ee + n) = v0;
                *(float2*)(Cp[q] + (size_t)cr1*Ee + n) = v1;
            }
        }
    }
}

// ---------------- single-B SIMT GEMM with M guard (z vectors: M = 10000, fp32 exact) ----------------
__global__ void __launch_bounds__(256) gemm320(
    const float* __restrict__ A, const int* __restrict__ rows, int M,
    const float* __restrict__ B, const float* __restrict__ bias,
    float* __restrict__ C)
{
    constexpr int BM = 64, BN = 64, BK = 16;
    __shared__ float As[BK][BM];
    __shared__ float Bs[BK][BN];
    const int tid = threadIdx.x;
    const int bm = blockIdx.y * BM;
    const int bn = blockIdx.x * BN;
    const int tcol = tid & 15;
    const int trow = tid >> 4;

    float acc[4][4];
    #pragma unroll
    for (int i = 0; i < 4; i++)
        #pragma unroll
        for (int j = 0; j < 4; j++) acc[i][j] = 0.f;

    const int aRow = tid >> 2;
    const int aCol = (tid & 3) << 2;
    int r = bm + aRow; if (r >= M) r = M - 1;
    const size_t ga = (size_t)(rows ? rows[r] : r) * Ee;
    const int bRow = tid >> 4;
    const int bCol = (tid & 15) << 2;

    for (int k0 = 0; k0 < Ee; k0 += BK) {
        float4 a4 = *(const float4*)(A + ga + k0 + aCol);
        float4 b4 = *(const float4*)(B + (size_t)(k0 + bRow)*Ee + bn + bCol);
        As[aCol+0][aRow] = a4.x; As[aCol+1][aRow] = a4.y;
        As[aCol+2][aRow] = a4.z; As[aCol+3][aRow] = a4.w;
        *(float4*)&Bs[bRow][bCol] = b4;
        __syncthreads();

        #pragma unroll
        for (int kk = 0; kk < BK; kk++) {
            float ar[4], br[4];
            #pragma unroll
            for (int i = 0; i < 4; i++) ar[i] = As[kk][trow*4 + i];
            #pragma unroll
            for (int j = 0; j < 4; j++) br[j] = Bs[kk][tcol*4 + j];
            #pragma unroll
            for (int i = 0; i < 4; i++)
                #pragma unroll
                for (int j = 0; j < 4; j++)
                    acc[i][j] += ar[i] * br[j];
        }
        __syncthreads();
    }

    float bb[4];
    #pragma unroll
    for (int j = 0; j < 4; j++) bb[j] = bias[bn + tcol*4 + j];
    #pragma unroll
    for (int i = 0; i < 4; i++) {
        int m = bm + trow*4 + i;
        if (m < M) {
            float4 o;
            o.x = acc[i][0] + bb[0];
            o.y = acc[i][1] + bb[1];
            o.z = acc[i][2] + bb[2];
            o.w = acc[i][3] + bb[3];
            *(float4*)(C + (size_t)m*Ee + bn + tcol*4) = o;
        }
    }
}

// ---------------- final 1-head attention (z-form scores) + fused output proj + ELU ----------------
__global__ void __launch_bounds__(256) final_attn2(
    const float* __restrict__ z_in, const float* __restrict__ z_out,
    const float* __restrict__ s0_in, const float* __restrict__ s0_out,
    const float* __restrict__ Oin, const float* __restrict__ Oout,
    const float* __restrict__ Vf, const float* __restrict__ Fmat,
    const float* __restrict__ fbias, float* __restrict__ out)
{
    __shared__ float szi[Ee], szo[Ee];
    __shared__ float sc[32];
    __shared__ float so[Ee];
    const int n = blockIdx.x;
    const int tid = threadIdx.x;
    const int warp = tid >> 5, lane = tid & 31;
    const float scale = 0.05590169943749474f;  // 1/sqrt(320)

    if (tid < Ee/4) {
        ((float4*)szi)[tid] = ((const float4*)(z_in + (size_t)n*Ee))[tid];
    } else if (tid >= 128 && tid < 128 + Ee/4) {
        ((float4*)szo)[tid - 128] = ((const float4*)(z_out + (size_t)n*Ee))[tid - 128];
    }
    __syncthreads();

    // 32 scores: score[m] = (z·b_m + s0) * scale, b_m = O row
    #pragma unroll
    for (int i = 0; i < 4; i++) {
        int m = warp*4 + i;
        const int half = m >> 4;
        const float4* br = (const float4*)((half ? Oout : Oin) + ((size_t)n*Ln + (m & 15)) * Ee);
        const float4* zz = (const float4*)(half ? szo : szi);
        float s = 0.f;
        #pragma unroll 1
        for (int f = lane; f < Ee/4; f += 32) {
            float4 bv = br[f];
            float4 zv = zz[f];
            s += zv.x*bv.x + zv.y*bv.y + zv.z*bv.z + zv.w*bv.w;
        }
        #pragma unroll
        for (int o = 16; o > 0; o >>= 1) s += __shfl_down_sync(0xffffffffu, s, o);
        if (lane == 0) sc[m] = (s + (half ? s0_out[n] : s0_in[n])) * scale;
    }
    __syncthreads();

    if (warp == 0) {
        float v = sc[lane];
        float mx = v;
        #pragma unroll
        for (int o = 16; o > 0; o >>= 1) mx = fmaxf(mx, __shfl_xor_sync(0xffffffffu, mx, o));
        float ex = expf(v - mx);
        float sm = ex;
        #pragma unroll
        for (int o = 16; o > 0; o >>= 1) sm += __shfl_xor_sync(0xffffffffu, sm, o);
        sc[lane] = ex / sm;
    }
    __syncthreads();

    for (int e = tid; e < Ee; e += 256) {
        const float* vr = Vf + (size_t)n*32*Ee + e;
        float a = 0.f;
        #pragma unroll
        for (int m = 0; m < 32; m++) a += sc[m] * vr[(size_t)m*Ee];
        so[e] = a;
    }
    __syncthreads();

    #pragma unroll
    for (int i = 0; i < 4; i++) {
        int j = warp*4 + i;
        if (j < OUTD) {
            float s = 0.f;
            for (int e = lane; e < Ee; e += 32) s += so[e] * Fmat[(size_t)e*OUTD + j];
            #pragma unroll
            for (int o = 16; o > 0; o >>= 1) s += __shfl_down_sync(0xffffffffu, s, o);
            if (lane == 0) {
                float x = s + fbias[j];
                out[(size_t)n*OUTD + j] = x > 0.f ? x : expm1f(x);
            }
        }
    }
}

// ---------------- host ----------------
#define GETSYM(p, s) do { void* _t; cudaGetSymbolAddress(&_t, s); p = decltype(p)(_t); } while (0)

extern "C" void kernel_launch(void* const* d_in, const int* in_sizes, int n_in,
                              void* d_out, int out_size)
{
    const float* X        = (const float*)d_in[0];
    const int*   in_idx   = (const int*)  d_in[1];
    const int*   out_idx  = (const int*)  d_in[2];
    const float* in_Wq    = (const float*)d_in[3];
    const float* in_Wk    = (const float*)d_in[4];
    const float* in_Wv    = (const float*)d_in[5];
    const float* in_qkv_w = (const float*)d_in[6];
    const float* in_qkv_b = (const float*)d_in[7];
    const float* in_o_w   = (const float*)d_in[8];
    const float* in_o_b   = (const float*)d_in[9];
    const float* out_Wq   = (const float*)d_in[10];
    const float* out_Wk   = (const float*)d_in[11];
    const float* out_Wv   = (const float*)d_in[12];
    const float* out_qkv_w= (const float*)d_in[13];
    const float* out_qkv_b= (const float*)d_in[14];
    const float* out_o_w  = (const float*)d_in[15];
    const float* out_o_b  = (const float*)d_in[16];
    const float* fin_qkv_w= (const float*)d_in[17];
    const float* fin_qkv_b= (const float*)d_in[18];
    const float* fin_o_w  = (const float*)d_in[19];
    const float* fin_o_b  = (const float*)d_in[20];
    const float* Wfin     = (const float*)d_in[21];
    float* out = (float*)d_out;

    float *Mq_in, *Mk_in, *Mv_in, *Mq_out, *Mk_out, *Mv_out;
    float *Qmat, *Kmat_in, *Kmat_out, *Vmat_in, *Vmat_out, *S_in, *S_out;
    float *T_in_o, *T_out_o, *T_fin_o;
    float *qbias, *kbias_in, *kbias_out, *vbias_in, *vbias_out;
    float *v1_in, *v1_out, *v2_in, *v2_out, *zeroE;
    float *Fmat, *fbias, *Oin, *Oout, *Vf, *z_in, *z_out, *s0_in, *s0_out;
    int *rows_in, *rows_out, *rows_q0;
    GETSYM(Mq_in, g_Mq_in);   GETSYM(Mk_in, g_Mk_in);   GETSYM(Mv_in, g_Mv_in);
    GETSYM(Mq_out, g_Mq_out); GETSYM(Mk_out, g_Mk_out); GETSYM(Mv_out, g_Mv_out);
    GETSYM(Qmat, g_Qmat);     GETSYM(Kmat_in, g_Kmat_in); GETSYM(Kmat_out, g_Kmat_out);
    GETSYM(Vmat_in, g_Vmat_in); GETSYM(Vmat_out, g_Vmat_out);
    GETSYM(S_in, g_S_in);     GETSYM(S_out, g_S_out);
    GETSYM(T_in_o, g_T_in_o); GETSYM(T_out_o, g_T_out_o); GETSYM(T_fin_o, g_T_fin_o);
    GETSYM(qbias, g_qbias);   GETSYM(kbias_in, g_kbias_in); GETSYM(kbias_out, g_kbias_out);
    GETSYM(vbias_in, g_vbias_in); GETSYM(vbias_out, g_vbias_out);
    GETSYM(v1_in, g_v1_in);   GETSYM(v1_out, g_v1_out);
    GETSYM(v2_in, g_v2_in);   GETSYM(v2_out, g_v2_out);
    GETSYM(zeroE, g_zeroE);
    GETSYM(Fmat, g_Fmat);     GETSYM(fbias, g_fbias);
    GETSYM(Oin, g_Oin); GETSYM(Oout, g_Oout);
    GETSYM(Vf, g_Vf);
    GETSYM(z_in, g_z_in); GETSYM(z_out, g_z_out);
    GETSYM(s0_in, g_s0_in); GETSYM(s0_out, g_s0_out);
    GETSYM(rows_in, g_rows_in); GETSYM(rows_out, g_rows_out); GETSYM(rows_q0, g_rows_q0);

    const int CB = 256;

    const int SMEM_FUSED = (3*128*68 + 128*17) * 4;      // 113024
    const int SMEM1 = (2*128*36 + 2*1*2048) * 4;         // 53248
    cudaFuncSetAttribute(gemm_attn_dual,  cudaFuncAttributeMaxDynamicSharedMemorySize, SMEM_FUSED);
    cudaFuncSetAttribute(gemm_tc_dual<1>, cudaFuncAttributeMaxDynamicSharedMemorySize, SMEM1);

    // 1) row gather tables + transposes of the three output-proj matrices
    build_rows<<<(Nn + CB - 1)/CB, CB>>>(in_idx, out_idx, rows_in, rows_out, rows_q0);
    dim3 tG(10, 10), tB(32, 8);
    transpose320<<<tG, tB>>>(in_o_w,  T_in_o);
    transpose320<<<tG, tB>>>(out_o_w, T_out_o);
    transpose320<<<tG, tB>>>(fin_o_w, T_fin_o);

    // 2) combined matrices pass 1. Kmat stays NATURAL (consumed by combine pass 2, not tc GEMM).
    CombineBatch cb;
    cb.A[0] = in_Wq;   cb.B[0] = in_qkv_w;            cb.C[0] = Mq_in;    cb.perm[0] = 1;
    cb.A[1] = in_Wk;   cb.B[1] = in_qkv_w + Ee*Ee;    cb.C[1] = Mk_in;    cb.perm[1] = 1;
    cb.A[2] = in_Wv;   cb.B[2] = in_qkv_w + 2*Ee*Ee;  cb.C[2] = Mv_in;    cb.perm[2] = 1;
    cb.A[3] = out_Wq;  cb.B[3] = out_qkv_w;           cb.C[3] = Mq_out;   cb.perm[3] = 1;
    cb.A[4] = out_Wk;  cb.B[4] = out_qkv_w + Ee*Ee;   cb.C[4] = Mk_out;   cb.perm[4] = 1;
    cb.A[5] = out_Wv;  cb.B[5] = out_qkv_w + 2*Ee*Ee; cb.C[5] = Mv_out;   cb.perm[5] = 1;
    cb.A[6] = T_in_o;  cb.B[6] = fin_qkv_w;           cb.C[6] = Qmat;     cb.perm[6] = 0;
    cb.A[7] = T_in_o;  cb.B[7] = fin_qkv_w + Ee*Ee;   cb.C[7] = Kmat_in;  cb.perm[7] = 0;
    cb.A[8] = T_out_o; cb.B[8] = fin_qkv_w + Ee*Ee;   cb.C[8] = Kmat_out; cb.perm[8] = 0;
    cb.A[9] = T_in_o;  cb.B[9] = fin_qkv_w + 2*Ee*Ee; cb.C[9] = Vmat_in;  cb.perm[9] = 1;
    cb.A[10]= T_out_o; cb.B[10]= fin_qkv_w + 2*Ee*Ee; cb.C[10]= Vmat_out; cb.perm[10]= 1;
    combine_batch<<<dim3(5, 5, NCOMB), CB>>>(cb);

    // 3) bias pass 1
    BiasBatch bb;
    bb.bo[0] = in_o_b;  bb.Bq[0] = fin_qkv_w;           bb.b2[0] = fin_qkv_b;          bb.out[0] = qbias;
    bb.bo[1] = in_o_b;  bb.Bq[1] = fin_qkv_w + Ee*Ee;   bb.b2[1] = fin_qkv_b + Ee;     bb.out[1] = kbias_in;
    bb.bo[2] = out_o_b; bb.Bq[2] = fin_qkv_w + Ee*Ee;   bb.b2[2] = fin_qkv_b + Ee;     bb.out[2] = kbias_out;
    bb.bo[3] = in_o_b;  bb.Bq[3] = fin_qkv_w + 2*Ee*Ee; bb.b2[3] = fin_qkv_b + 2*Ee;   bb.out[3] = vbias_in;
    bb.bo[4] = out_o_b; bb.Bq[4] = fin_qkv_w + 2*Ee*Ee; bb.b2[4] = fin_qkv_b + 2*Ee;   bb.out[4] = vbias_out;
    bias_batch<<<dim3(40, NBIAS), CB>>>(bb);

    // 4) combine pass 2: S = Qmat @ Kmat^T (natural layout; needs pass 1 outputs)
    CombineBatch cb2;
    cb2.A[0] = Qmat; cb2.B[0] = Kmat_in;  cb2.C[0] = S_in;  cb2.perm[0] = 0;
    cb2.A[1] = Qmat; cb2.B[1] = Kmat_out; cb2.C[1] = S_out; cb2.perm[1] = 0;
    combine_batch<<<dim3(5, 5, 2), CB>>>(cb2);

    // 5) bias pass 2: v1 = Qmat@kbias, v2 = Kmat@qbias (zero offset)
    BiasBatch bb2;
    bb2.bo[0] = kbias_in;  bb2.Bq[0] = Qmat;     bb2.b2[0] = zeroE; bb2.out[0] = v1_in;
    bb2.bo[1] = kbias_out; bb2.Bq[1] = Qmat;     bb2.b2[1] = zeroE; bb2.out[1] = v1_out;
    bb2.bo[2] = qbias;     bb2.Bq[2] = Kmat_in;  bb2.b2[2] = zeroE; bb2.out[2] = v2_in;
    bb2.bo[3] = qbias;     bb2.Bq[3] = Kmat_out; bb2.b2[3] = zeroE; bb2.out[3] = v2_out;
    bb2.bo[4] = qbias;     bb2.Bq[4] = Kmat_in;  bb2.b2[4] = zeroE; bb2.out[4] = v2_in;  // dup, unused
    bias_batch<<<dim3(40, 4), CB>>>(bb2);

    // 6) readout fold
    combine_fmat_w<<<(Ee*OUTD + 7)/8, CB>>>(T_fin_o, Wfin, Fmat);
    combine_fbias_w<<<1, CB>>>(fin_o_b, Wfin, fbias);

    const int Mfull = Nn * Ln;           // 160000 = 1250 * 128

    // 7) BOTH layers: fused QKV-GEMM + attention, writing Oin/Oout directly
    DualArgs d3;
    d3.A[0] = X;  d3.A[1] = X;
    d3.rows[0] = rows_in;  d3.rows[1] = rows_out;
    d3.B[0][0] = Mq_in;  d3.B[0][1] = Mk_in;  d3.B[0][2] = Mv_in;
    d3.B[1][0] = Mq_out; d3.B[1][1] = Mk_out; d3.B[1][2] = Mv_out;
    d3.bias[0][0] = in_qkv_b;  d3.bias[0][1] = in_qkv_b + Ee;  d3.bias[0][2] = in_qkv_b + 2*Ee;
    d3.bias[1][0] = out_qkv_b; d3.bias[1][1] = out_qkv_b + Ee; d3.bias[1][2] = out_qkv_b + 2*Ee;
    d3.C[0][0] = Oin;  d3.C[0][1] = nullptr; d3.C[0][2] = nullptr;
    d3.C[1][0] = Oout; d3.C[1][1] = nullptr; d3.C[1][2] = nullptr;
    d3.out_grp = 16; d3.out_str = 16; d3.out_off[0] = 0; d3.out_off[1] = 0;
    gemm_attn_dual<<<dim3(Ee/64, Mfull/128, 2), 256, SMEM_FUSED>>>(d3);

    // 8) Vf only (Kf eliminated algebraically): interleaved halves
    DualArgs d1;
    d1.A[0] = Oin;  d1.A[1] = Oout;
    d1.rows[0] = nullptr; d1.rows[1] = nullptr;
    d1.B[0][0] = Vmat_in;  d1.B[0][1] = nullptr; d1.B[0][2] = nullptr;
    d1.B[1][0] = Vmat_out; d1.B[1][1] = nullptr; d1.B[1][2] = nullptr;
    d1.bias[0][0] = vbias_in;  d1.bias[0][1] = nullptr; d1.bias[0][2] = nullptr;
    d1.bias[1][0] = vbias_out; d1.bias[1][1] = nullptr; d1.bias[1][2] = nullptr;
    d1.C[0][0] = Vf; d1.C[0][1] = nullptr; d1.C[0][2] = nullptr;
    d1.C[1][0] = Vf; d1.C[1][1] = nullptr; d1.C[1][2] = nullptr;
    d1.out_grp = 16; d1.out_str = 32; d1.out_off[0] = 0; d1.out_off[1] = 16;
    gemm_tc_dual<1><<<dim3(Ee/64, Mfull/128, 2), 256, SMEM1>>>(d1);

    // 9) z = gather(Oin)[n*16] @ S + v2  (replaces q0 and the entire Kf GEMM)
    gemm320<<<dim3(Ee/64, (Nn + 63)/64), 256>>>(Oin, rows_q0, Nn, S_in,  v2_in,  z_in);
    gemm320<<<dim3(Ee/64, (Nn + 63)/64), 256>>>(Oin, rows_q0, Nn, S_out, v2_out, z_out);

    // 10) s0[n] = a·v1 + qbias·kbias
    s0_kernel<<<(Nn*32 + CB - 1)/CB, CB>>>(Oin, v1_in, v1_out, qbias, kbias_in, kbias_out, s0_in, s0_out);

    // 11) final attention (z-form scores) + fused readout + ELU
    final_attn2<<<Nn, 256>>>(z_in, z_out, s0_in, s0_out, Oin, Oout, Vf, Fmat, fbias, out);
}